// round 3
// baseline (speedup 1.0000x reference)
#include <cuda_runtime.h>
#include <math.h>
#include <stdint.h>

#define LL 25
#define CC 64
#define NMAX 4096
#define EMAX 32768
#define GG 45
#define EPSF 1e-6f

__constant__ int c_deg[25] = {0,1,1,1,2,2,2,2,2,3,3,3,3,3,3,3,4,4,4,4,4,4,4,4,4};

// ---------------- scratch ----------------
__device__ float g_x1[(size_t)NMAX*LL*CC];
__device__ float g_rad[(size_t)EMAX*64];
__device__ float g_logits[(size_t)EMAX*8];
__device__ float g_segmax[NMAX*8];
__device__ float g_denom[NMAX*8];
__device__ float g_agg[(size_t)NMAX*LL*128];
__device__ float g_x2[(size_t)NMAX*LL*CC];
__device__ float g_gg[(size_t)NMAX*GG*128];

// transposed weights (contiguous along k for vector loads)
__device__ float g_wtE[64*64];        // [c][k]
__device__ float g_wtR1[64*64];
__device__ float g_wtR2[64*64];
__device__ float g_wtM[5*64*128];     // [d][c][k] k<128
__device__ float g_wtA[128*64];       // [o][k]
__device__ float g_wtV[5*128*64];     // [d][o][k] k<64
__device__ float g_wtO[5*64*128];     // [d][c][k] k<128
__device__ float g_wtF1[5*128*64];    // [d][f][k] k<64
__device__ float g_wtG[128*128];      // [o][k]
__device__ float g_wtF2[5*64*128];    // [d][c][k] k<128
__device__ float g_tg[GG*28];         // to_grid padded [p][l] l<28
__device__ float g_fg[LL*48];         // from_grid padded [l][p] p<48

__device__ __forceinline__ float sigmoidf_(float x){ return 1.f/(1.f+__expf(-x)); }

__device__ __forceinline__ void atomicMaxF(float* addr, float v){
    if (v >= 0.f) atomicMax((int*)addr, __float_as_int(v));
    else          atomicMin((unsigned int*)addr, __float_as_uint(v));
}

__device__ __forceinline__ float dot4a(float4 a, float4 b, float acc){
    acc = fmaf(a.x, b.x, acc); acc = fmaf(a.y, b.y, acc);
    acc = fmaf(a.z, b.z, acc); acc = fmaf(a.w, b.w, acc);
    return acc;
}

// ------------- vectorized row-tiled GEMM helpers -------------
// A smem [rows][128], Wt global row c contiguous (128), out smem [rows][64]
template<int R>
__device__ __forceinline__ void mmv4_128(const float* __restrict__ sA,
                                         const float* __restrict__ Wt,
                                         float* __restrict__ sOut,
                                         int base, int c, float scale){
    float acc[R];
    #pragma unroll
    for (int rr=0; rr<R; rr++) acc[rr]=0.f;
    const float4* wrow = (const float4*)(Wt + c*128);
    #pragma unroll 8
    for (int q=0; q<32; q++){
        float4 w = __ldg(&wrow[q]);
        #pragma unroll
        for (int rr=0; rr<R; rr++){
            float4 a = *(const float4*)&sA[(base+rr)*128 + 4*q];
            acc[rr] = dot4a(a, w, acc[rr]);
        }
    }
    #pragma unroll
    for (int rr=0; rr<R; rr++) sOut[(base+rr)*64+c] = acc[rr]*scale;
}

// A smem [rows][64], Wt row o contiguous (64), out smem [rows][128]
template<int R>
__device__ __forceinline__ void mmv4_64(const float* __restrict__ sA,
                                        const float* __restrict__ Wt,
                                        float* __restrict__ sOut,
                                        int base, int o, float scale){
    float acc[R];
    #pragma unroll
    for (int rr=0; rr<R; rr++) acc[rr]=0.f;
    const float4* wrow = (const float4*)(Wt + o*64);
    #pragma unroll 8
    for (int q=0; q<16; q++){
        float4 w = __ldg(&wrow[q]);
        #pragma unroll
        for (int rr=0; rr<R; rr++){
            float4 a = *(const float4*)&sA[(base+rr)*64 + 4*q];
            acc[rr] = dot4a(a, w, acc[rr]);
        }
    }
    #pragma unroll
    for (int rr=0; rr<R; rr++) sOut[(base+rr)*128+o] = acc[rr]*scale;
}

// A smem [rows][128], Wt row c contiguous (128), out global [rows][64] + residual
template<int R>
__device__ __forceinline__ void mmv4_out(const float* __restrict__ sA,
                                         const float* __restrict__ Wt,
                                         const float* __restrict__ res,
                                         float* __restrict__ outp,
                                         int base, int c){
    float acc[R];
    #pragma unroll
    for (int rr=0; rr<R; rr++) acc[rr]=0.f;
    const float4* wrow = (const float4*)(Wt + c*128);
    #pragma unroll 8
    for (int q=0; q<32; q++){
        float4 w = __ldg(&wrow[q]);
        #pragma unroll
        for (int rr=0; rr<R; rr++){
            float4 a = *(const float4*)&sA[(base+rr)*128 + 4*q];
            acc[rr] = dot4a(a, w, acc[rr]);
        }
    }
    #pragma unroll
    for (int rr=0; rr<R; rr++)
        outp[(base+rr)*64+c] = acc[rr] + res[(base+rr)*64+c];
}

// ff1: A smem [rows][64], Wt row f contiguous (64), out regs t1[base..base+R)
template<int R>
__device__ __forceinline__ void ff1_rows(const float* __restrict__ sA,
                                         const float* __restrict__ Wt,
                                         float* __restrict__ t1,
                                         int base, int f){
    float acc[R];
    #pragma unroll
    for (int rr=0; rr<R; rr++) acc[rr]=0.f;
    const float4* wrow = (const float4*)(Wt + f*64);
    #pragma unroll 8
    for (int q=0; q<16; q++){
        float4 w = __ldg(&wrow[q]);
        #pragma unroll
        for (int rr=0; rr<R; rr++){
            float4 a = *(const float4*)&sA[(base+rr)*64 + 4*q];
            acc[rr] = dot4a(a, w, acc[rr]);
        }
    }
    #pragma unroll
    for (int rr=0; rr<R; rr++) t1[base+rr] = acc[rr];
}

// ---------------- kernels ----------------

__global__ void k_prep(const float* __restrict__ W_edge, const float* __restrict__ W_r1,
                       const float* __restrict__ W_r2, const float* __restrict__ W_msg,
                       const float* __restrict__ W_alpha, const float* __restrict__ W_val,
                       const float* __restrict__ W_out, const float* __restrict__ W_ff1,
                       const float* __restrict__ W_grid, const float* __restrict__ W_ff2,
                       const float* __restrict__ to_grid, const float* __restrict__ from_grid){
    int i0 = blockIdx.x*blockDim.x + threadIdx.x;
    int stride = gridDim.x*blockDim.x;
    for (int i=i0; i<4096; i+=stride){
        int c=i>>6, k=i&63;
        g_wtE[i]  = W_edge[k*64+c];
        g_wtR1[i] = W_r1[k*64+c];
        g_wtR2[i] = W_r2[k*64+c];
    }
    for (int i=i0; i<40960; i+=stride){
        int d=i/8192, r=i%8192;
        { int c=r/128, k=r%128;  g_wtM[i] = W_msg[d*8192+k*64+c];
                                 g_wtO[i] = W_out[d*8192+k*64+c];
                                 g_wtF2[i]= W_ff2[d*8192+k*64+c]; }
        { int o=r/64,  k=r%64;   g_wtV[i] = W_val[d*8192+k*128+o];
                                 g_wtF1[i]= W_ff1[d*8192+k*128+o]; }
    }
    for (int i=i0; i<8192; i+=stride){
        int o=i>>6, k=i&63;
        g_wtA[i] = W_alpha[k*128+o];
    }
    for (int i=i0; i<16384; i+=stride){
        int o=i>>7, k=i&127;
        g_wtG[i] = W_grid[k*128+o];
    }
    for (int i=i0; i<GG*28; i+=stride){
        int p=i/28, l=i%28;
        g_tg[i] = (l<25) ? to_grid[p*25+l] : 0.f;
    }
    for (int i=i0; i<LL*48; i+=stride){
        int l=i/48, p=i%48;
        g_fg[i] = (p<GG) ? from_grid[l*GG+p] : 0.f;
    }
}

__global__ void k_init(int N){
    int i = blockIdx.x*blockDim.x + threadIdx.x;
    int stride = gridDim.x*blockDim.x;
    int tot = N*LL*128;
    for (int idx=i; idx<tot; idx+=stride) g_agg[idx] = 0.f;
    if (i < N*8){ g_denom[i] = 0.f; g_segmax[i] = -1e30f; }
}

__global__ void k_norm1(const float* __restrict__ nf, const float* __restrict__ w, int N){
    int n = blockIdx.x; int t = threadIdx.x;
    __shared__ float ssq[5], sinv[5];
    if (t < 5) ssq[t] = 0.f;
    __syncthreads();
    const float* src = nf + (size_t)n*1600;
    #pragma unroll
    for (int d=0; d<5; d++){
        int b = d*d*64, cnt = (2*d+1)*64;
        float a = 0.f;
        for (int idx=t; idx<cnt; idx+=128){ float v = src[b+idx]; a += v*v; }
        #pragma unroll
        for (int off=16; off>0; off>>=1) a += __shfl_down_sync(0xffffffffu, a, off);
        if ((t & 31) == 0) atomicAdd(&ssq[d], a);
    }
    __syncthreads();
    if (t < 5) sinv[t] = rsqrtf(ssq[t] / ((2.f*t+1.f)*64.f) + EPSF);
    __syncthreads();
    float* dst = g_x1 + (size_t)n*1600;
    for (int idx=t; idx<1600; idx+=128){
        int l = idx>>6, c = idx&63;
        int d = c_deg[l];
        dst[idx] = src[idx] * sinv[d] * __ldg(&w[d*64+c]);
    }
}

// 2 edges per block, 64 threads each; all stages full-width
__global__ __launch_bounds__(128)
void k_edge_logits(const float* __restrict__ dist, const int* __restrict__ species,
                   const int* __restrict__ senders, const int* __restrict__ receivers,
                   const float* __restrict__ wigner,
                   const float* __restrict__ emb_src, const float* __restrict__ emb_dst,
                   const float* __restrict__ b_r1, const float* __restrict__ b_r2,
                   const float* __restrict__ alpha_vec, int E){
    int t = threadIdx.x;
    int sub = t >> 6;
    int c = t & 63;
    int e = blockIdx.x*2 + sub;
    bool valid = (e < E);
    if (!valid) e = E-1;

    __shared__ float se[2][64], sr1[2][64], sm0[2][128], sh0[2][64];

    int s = senders[e], r = receivers[e];
    int sps = species[s], spr = species[r];

    // stage 1: e = dist @ W_edge + embeddings
    {
        float acc = __ldg(&emb_src[sps*64+c]) + __ldg(&emb_dst[spr*64+c]);
        const float4* db = (const float4*)(dist + (size_t)e*64);
        const float4* wrow = (const float4*)(g_wtE + c*64);
        #pragma unroll
        for (int q=0; q<16; q++) acc = dot4a(__ldg(&db[q]), __ldg(&wrow[q]), acc);
        se[sub][c] = acc;
    }
    __syncthreads();
    // stage 2: silu(e @ W_r1 + b1)
    {
        float acc = __ldg(&b_r1[c]);
        const float4* wrow = (const float4*)(g_wtR1 + c*64);
        #pragma unroll
        for (int q=0; q<16; q++){
            float4 a = *(const float4*)&se[sub][4*q];
            acc = dot4a(a, __ldg(&wrow[q]), acc);
        }
        sr1[sub][c] = acc * sigmoidf_(acc);
    }
    __syncthreads();
    // stage 3: rad = sr1 @ W_r2 + b2
    float rad;
    {
        float acc = __ldg(&b_r2[c]);
        const float4* wrow = (const float4*)(g_wtR2 + c*64);
        #pragma unroll
        for (int q=0; q<16; q++){
            float4 a = *(const float4*)&sr1[sub][4*q];
            acc = dot4a(a, __ldg(&wrow[q]), acc);
        }
        rad = acc;
        g_rad[(size_t)e*64+c] = acc;
    }
    // m0: row 0 of rotated concat message (both halves per thread)
    {
        const float* wg = wigner + (size_t)e*625;
        const float* xs = g_x1 + (size_t)s*1600 + c;
        const float* xr = g_x1 + (size_t)r*1600 + c;
        float a0=0.f, a1=0.f;
        #pragma unroll
        for (int j=0; j<25; j++){
            float w = __ldg(&wg[j]);
            a0 = fmaf(w, xs[j*64], a0);
            a1 = fmaf(w, xr[j*64], a1);
        }
        sm0[sub][c] = a0; sm0[sub][64+c] = a1;
    }
    __syncthreads();
    // h0 = (m0 @ W_msg0) * rad, gated
    {
        float acc = 0.f;
        const float4* wrow = (const float4*)(g_wtM + c*128);
        #pragma unroll
        for (int q=0; q<32; q++){
            float4 a = *(const float4*)&sm0[sub][4*q];
            acc = dot4a(a, __ldg(&wrow[q]), acc);
        }
        acc *= rad;
        sh0[sub][c] = acc * sigmoidf_(acc);
    }
    __syncthreads();
    // alpha: two outputs per thread (o=c, o=c+64)
    {
        float a0=0.f, a1=0.f;
        const float4* w0 = (const float4*)(g_wtA + c*64);
        const float4* w1 = (const float4*)(g_wtA + (c+64)*64);
        #pragma unroll
        for (int q=0; q<16; q++){
            float4 a = *(const float4*)&sh0[sub][4*q];
            a0 = dot4a(a, __ldg(&w0[q]), a0);
            a1 = dot4a(a, __ldg(&w1[q]), a1);
        }
        a0 = (a0 > 0.f) ? a0 : 0.2f*a0;
        a1 = (a1 > 0.f) ? a1 : 0.2f*a1;
        float p0 = a0 * __ldg(&alpha_vec[c]);
        float p1 = a1 * __ldg(&alpha_vec[c+64]);
        #pragma unroll
        for (int off=8; off>0; off>>=1){
            p0 += __shfl_down_sync(0xffffffffu, p0, off);
            p1 += __shfl_down_sync(0xffffffffu, p1, off);
        }
        if (((t & 15) == 0) && valid){
            g_logits[(size_t)e*8 + (c>>4)]     = p0;
            g_logits[(size_t)e*8 + 4 + (c>>4)] = p1;
        }
    }
}

__global__ void k_segmax(const int* __restrict__ receivers, int E){
    int i = blockIdx.x*blockDim.x + threadIdx.x;
    if (i >= E*8) return;
    int e = i>>3, hh = i&7;
    atomicMaxF(&g_segmax[receivers[e]*8+hh], g_logits[i]);
}

__global__ void k_denom(const int* __restrict__ receivers, int E){
    int i = blockIdx.x*blockDim.x + threadIdx.x;
    if (i >= E*8) return;
    int e = i>>3, hh = i&7;
    int r = receivers[e];
    atomicAdd(&g_denom[r*8+hh], __expf(g_logits[i] - g_segmax[r*8+hh]));
}

// main edge kernel
__global__ __launch_bounds__(128)
void k_edge_main(const int* __restrict__ senders, const int* __restrict__ receivers,
                 const float* __restrict__ wigner, int E){
    int e = blockIdx.x; int t = threadIdx.x;
    __shared__ float swig[25*28];    // padded rows
    __shared__ float swigT[25*28];   // swigT[i][j] = wig[j][i]
    __shared__ float sbuf[25*128];   // msgrot, then v, then rotated-back v
    __shared__ float sh[25*64];
    __shared__ float srad[64], ssig[64], sattn[8];

    int s = senders[e], r = receivers[e];
    for (int i=t; i<700; i+=128){
        int row=i/28, col=i-row*28;
        swig[i]  = (col<25) ? wigner[(size_t)e*625 + row*25 + col] : 0.f;
        swigT[i] = (col<25) ? wigner[(size_t)e*625 + col*25 + row] : 0.f;
    }
    if (t < 64) srad[t] = g_rad[(size_t)e*64+t];
    if (t < 8){
        float lg = g_logits[(size_t)e*8+t];
        sattn[t] = __expf(lg - g_segmax[r*8+t]) / (g_denom[r*8+t] + EPSF);
    }
    __syncthreads();

    // forward rotation: sbuf[i][t] = sum_j wig[i][j] * mc[j]
    float mc[28];
    {
        const float* xb = (t < 64) ? (g_x1 + (size_t)s*1600 + t)
                                   : (g_x1 + (size_t)r*1600 + (t-64));
        #pragma unroll
        for (int j=0; j<25; j++) mc[j] = xb[j*64];
        mc[25]=mc[26]=mc[27]=0.f;
    }
    #pragma unroll 1
    for (int i=0; i<25; i++){
        float acc = 0.f;
        #pragma unroll
        for (int q=0; q<7; q++){
            float4 w = *(const float4*)&swig[i*28 + 4*q];
            acc = fmaf(w.x, mc[4*q+0], acc);
            acc = fmaf(w.y, mc[4*q+1], acc);
            acc = fmaf(w.z, mc[4*q+2], acc);
            acc = fmaf(w.w, mc[4*q+3], acc);
        }
        sbuf[i*128+t] = acc;
    }
    __syncthreads();

    // h0 + gate
    if (t < 64){
        float acc = 0.f;
        const float4* wrow = (const float4*)(g_wtM + t*128);
        #pragma unroll
        for (int q=0; q<32; q++){
            float4 a = *(const float4*)&sbuf[4*q];
            acc = dot4a(a, __ldg(&wrow[q]), acc);
        }
        acc *= srad[t];
        float sg = sigmoidf_(acc);
        ssig[t] = sg;
        sh[t] = acc*sg;
    }
    __syncthreads();

    // remaining degrees of h (row split between half-blocks)
    {
        int c = t & 63;
        float scale = srad[c]*ssig[c];
        if (t < 64){
            mmv4_128<3>(sbuf, g_wtM + 1*8192, sh, 1,  c, scale);
            mmv4_128<9>(sbuf, g_wtM + 4*8192, sh, 16, c, scale);
        } else {
            mmv4_128<5>(sbuf, g_wtM + 2*8192, sh, 4,  c, scale);
            mmv4_128<7>(sbuf, g_wtM + 3*8192, sh, 9,  c, scale);
        }
    }
    __syncthreads();

    // v = h @ W_val[deg] * attn  (writes sbuf, column t — column-private)
    {
        float attn = sattn[t>>4];
        mmv4_64<1>(sh, g_wtV + 0*8192, sbuf, 0,  t, attn);
        mmv4_64<3>(sh, g_wtV + 1*8192, sbuf, 1,  t, attn);
        mmv4_64<5>(sh, g_wtV + 2*8192, sbuf, 4,  t, attn);
        mmv4_64<7>(sh, g_wtV + 3*8192, sbuf, 9,  t, attn);
        mmv4_64<9>(sh, g_wtV + 4*8192, sbuf, 16, t, attn);
    }
    // rotate back, column-private in/out (no sync needed)
    #pragma unroll
    for (int j=0; j<25; j++) mc[j] = sbuf[j*128+t];
    mc[25]=mc[26]=mc[27]=0.f;
    #pragma unroll 1
    for (int i=0; i<25; i++){
        float acc = 0.f;
        #pragma unroll
        for (int q=0; q<7; q++){
            float4 w = *(const float4*)&swigT[i*28 + 4*q];
            acc = fmaf(w.x, mc[4*q+0], acc);
            acc = fmaf(w.y, mc[4*q+1], acc);
            acc = fmaf(w.z, mc[4*q+2], acc);
            acc = fmaf(w.w, mc[4*q+3], acc);
        }
        sbuf[i*128+t] = acc;
    }
    __syncthreads();

    // one bulk reduce-add of the whole 25x128 tile into g_agg[r]
    if (t == 0){
        asm volatile("fence.proxy.async.shared::cta;" ::: "memory");
        float* dst = g_agg + (size_t)r*3200;
        uint32_t sptr;
        asm("{ .reg .u64 tt; cvta.to.shared.u64 tt, %1; cvt.u32.u64 %0, tt; }"
            : "=r"(sptr) : "l"(sbuf));
        asm volatile("cp.reduce.async.bulk.global.shared::cta.bulk_group.add.f32 [%0], [%1], %2;"
                     :: "l"(dst), "r"(sptr), "r"(12800) : "memory");
        asm volatile("cp.async.bulk.commit_group;" ::: "memory");
        asm volatile("cp.async.bulk.wait_group 0;" ::: "memory");
    }
    __syncthreads();
}

__global__ __launch_bounds__(128)
void k_wout(const float* __restrict__ nf, int N){
    int n = blockIdx.x; int t = threadIdx.x;
    __shared__ float sagg[25*128];
    {
        const float4* src = (const float4*)(g_agg + (size_t)n*3200);
        float4* dst4 = (float4*)sagg;
        for (int i=t; i<800; i+=128) dst4[i] = src[i];
    }
    __syncthreads();
    int c = t & 63;
    const float* res = nf + (size_t)n*1600;
    float* outp = g_x2 + (size_t)n*1600;
    if (t < 64){
        mmv4_out<1>(sagg, g_wtO + 0*8192, res, outp, 0,  c);
        mmv4_out<3>(sagg, g_wtO + 1*8192, res, outp, 1,  c);
        mmv4_out<9>(sagg, g_wtO + 4*8192, res, outp, 16, c);
    } else {
        mmv4_out<5>(sagg, g_wtO + 2*8192, res, outp, 4,  c);
        mmv4_out<7>(sagg, g_wtO + 3*8192, res, outp, 9,  c);
    }
}

// FFN part A: norm2 -> ff1(regs) -> to_grid -> W_grid+silu
__global__ __launch_bounds__(128)
void k_ffn_a(const float* __restrict__ norm2w, const float* __restrict__ b_grid, int N){
    int n = blockIdx.x; int t = threadIdx.x;
    __shared__ float sx[25*64];
    __shared__ float sg[GG*128];
    __shared__ float stg[GG*28];
    __shared__ float ssq[5], sinv[5];

    if (t < 5) ssq[t] = 0.f;
    for (int i=t; i<GG*28; i+=128) stg[i] = g_tg[i];
    __syncthreads();

    const float* xb = g_x2 + (size_t)n*1600;
    #pragma unroll
    for (int d=0; d<5; d++){
        int b = d*d*64, cnt = (2*d+1)*64;
        float a = 0.f;
        for (int idx=t; idx<cnt; idx+=128){ float v = xb[b+idx]; sx[b+idx] = v; a += v*v; }
        #pragma unroll
        for (int off=16; off>0; off>>=1) a += __shfl_down_sync(0xffffffffu, a, off);
        if ((t & 31) == 0) atomicAdd(&ssq[d], a);
    }
    __syncthreads();
    if (t < 5) sinv[t] = rsqrtf(ssq[t] / ((2.f*t+1.f)*64.f) + EPSF);
    __syncthreads();
    for (int idx=t; idx<1600; idx+=128){
        int l = idx>>6, c = idx&63;
        int d = c_deg[l];
        sx[idx] *= sinv[d] * __ldg(&norm2w[d*64+c]);
    }
    __syncthreads();

    // ff1 into registers (thread t owns column t of [25][128])
    float t1[28];
    ff1_rows<1>(sx, g_wtF1 + 0*8192, t1, 0,  t);
    ff1_rows<3>(sx, g_wtF1 + 1*8192, t1, 1,  t);
    ff1_rows<5>(sx, g_wtF1 + 2*8192, t1, 4,  t);
    ff1_rows<7>(sx, g_wtF1 + 3*8192, t1, 9,  t);
    ff1_rows<9>(sx, g_wtF1 + 4*8192, t1, 16, t);
    t1[25]=t1[26]=t1[27]=0.f;

    // to_grid
    #pragma unroll 1
    for (int p=0; p<GG; p++){
        float acc = 0.f;
        #pragma unroll
        for (int q=0; q<7; q++){
            float4 w = *(const float4*)&stg[p*28 + 4*q];
            acc = fmaf(w.x, t1[4*q+0], acc);
            acc = fmaf(w.y, t1[4*q+1], acc);
            acc = fmaf(w.z, t1[4*q+2], acc);
            acc = fmaf(w.w, t1[4*q+3], acc);
        }
        sg[p*128+t] = acc;
    }
    __syncthreads();

    // pointwise grid GEMM + silu (5-row tiles, 45 = 9*5)
    float bg = __ldg(&b_grid[t]);
    const float4* wtg = (const float4*)(g_wtG + t*128);
    #pragma unroll 1
    for (int pt=0; pt<9; pt++){
        float acc[5] = {0.f,0.f,0.f,0.f,0.f};
        #pragma unroll 8
        for (int q=0; q<32; q++){
            float4 w = __ldg(&wtg[q]);
            #pragma unroll
            for (int rr=0; rr<5; rr++){
                float4 a = *(const float4*)&sg[(pt*5+rr)*128 + 4*q];
                acc[rr] = dot4a(a, w, acc[rr]);
            }
        }
        #pragma unroll
        for (int rr=0; rr<5; rr++){
            float z = acc[rr] + bg;
            g_gg[((size_t)n*GG + pt*5+rr)*128 + t] = z * sigmoidf_(z);
        }
    }
}

// FFN part B: from_grid(regs) -> ff2 + residual -> out
__global__ __launch_bounds__(128)
void k_ffn_b(float* __restrict__ out, int N){
    int n = blockIdx.x; int t = threadIdx.x;
    __shared__ float sfg[LL*48];
    __shared__ float sy2[25*128];

    for (int i=t; i<LL*48; i+=128) sfg[i] = g_fg[i];

    float gg[48];
    {
        const float* src = g_gg + (size_t)n*GG*128 + t;
        #pragma unroll
        for (int p=0; p<GG; p++) gg[p] = src[p*128];
        gg[45]=gg[46]=gg[47]=0.f;
    }
    __syncthreads();

    #pragma unroll 1
    for (int l=0; l<25; l++){
        float acc = 0.f;
        #pragma unroll
        for (int q=0; q<12; q++){
            float4 w = *(const float4*)&sfg[l*48 + 4*q];
            acc = fmaf(w.x, gg[4*q+0], acc);
            acc = fmaf(w.y, gg[4*q+1], acc);
            acc = fmaf(w.z, gg[4*q+2], acc);
            acc = fmaf(w.w, gg[4*q+3], acc);
        }
        sy2[l*128+t] = acc;
    }
    __syncthreads();

    int c = t & 63;
    const float* res = g_x2 + (size_t)n*1600;
    float* outp = out + (size_t)n*1600;
    if (t < 64){
        mmv4_out<1>(sy2, g_wtF2 + 0*8192, res, outp, 0,  c);
        mmv4_out<3>(sy2, g_wtF2 + 1*8192, res, outp, 1,  c);
        mmv4_out<9>(sy2, g_wtF2 + 4*8192, res, outp, 16, c);
    } else {
        mmv4_out<5>(sy2, g_wtF2 + 2*8192, res, outp, 4,  c);
        mmv4_out<7>(sy2, g_wtF2 + 3*8192, res, outp, 9,  c);
    }
}

// ---------------- host launcher ----------------
extern "C" void kernel_launch(void* const* d_in, const int* in_sizes, int n_in,
                              void* d_out, int out_size){
    int p = (in_sizes[6] <= 4) ? 7 : 6;

    const float* node_feats = (const float*)d_in[0];
    const int*   species    = (const int*)  d_in[1];
    const float* edge_dist  = (const float*)d_in[2];
    const int*   senders    = (const int*)  d_in[3];
    const int*   receivers  = (const int*)  d_in[4];
    const float* wigner     = (const float*)d_in[5];
    const float* norm1_w    = (const float*)d_in[p+0];
    const float* norm2_w    = (const float*)d_in[p+1];
    const float* W_edge     = (const float*)d_in[p+2];
    const float* emb_src    = (const float*)d_in[p+3];
    const float* emb_dst    = (const float*)d_in[p+4];
    const float* W_r1       = (const float*)d_in[p+5];
    const float* b_r1       = (const float*)d_in[p+6];
    const float* W_r2       = (const float*)d_in[p+7];
    const float* b_r2       = (const float*)d_in[p+8];
    const float* W_msg      = (const float*)d_in[p+9];
    const float* W_alpha    = (const float*)d_in[p+10];
    const float* alpha_vec  = (const float*)d_in[p+11];
    const float* W_val      = (const float*)d_in[p+12];
    const float* W_out      = (const float*)d_in[p+13];
    const float* W_ff1      = (const float*)d_in[p+14];
    const float* to_grid    = (const float*)d_in[p+15];
    const float* from_grid  = (const float*)d_in[p+16];
    const float* W_grid     = (const float*)d_in[p+17];
    const float* b_grid     = (const float*)d_in[p+18];
    const float* W_ff2      = (const float*)d_in[p+19];

    int N = in_sizes[0] / (LL*CC);
    int E = in_sizes[3];
    if (N > NMAX) N = NMAX;
    if (E > EMAX) E = EMAX;

    k_prep<<<128, 256>>>(W_edge, W_r1, W_r2, W_msg, W_alpha, W_val,
                         W_out, W_ff1, W_grid, W_ff2, to_grid, from_grid);
    k_init<<<2048, 256>>>(N);
    k_norm1<<<N, 128>>>(node_feats, norm1_w, N);
    k_edge_logits<<<(E+1)/2, 128>>>(edge_dist, species, senders, receivers, wigner,
                                    emb_src, emb_dst, b_r1, b_r2, alpha_vec, E);
    int segthreads = 256;
    int segblocks = (E*8 + segthreads - 1) / segthreads;
    k_segmax<<<segblocks, segthreads>>>(receivers, E);
    k_denom<<<segblocks, segthreads>>>(receivers, E);
    k_edge_main<<<E, 128>>>(senders, receivers, wigner, E);
    k_wout<<<N, 128>>>(node_feats, N);
    k_ffn_a<<<N, 128>>>(norm2_w, b_grid, N);
    k_ffn_b<<<N, 128>>>((float*)d_out, N);
}

// round 4
// speedup vs baseline: 1.6865x; 1.6865x over previous
#include <cuda_runtime.h>
#include <math.h>
#include <stdint.h>

#define LL 25
#define CC 64
#define NMAX 4096
#define EMAX 32768
#define GG 45
#define EPSF 1e-6f

__constant__ int c_deg[25] = {0,1,1,1,2,2,2,2,2,3,3,3,3,3,3,3,4,4,4,4,4,4,4,4,4};

// ---------------- scratch ----------------
__device__ float g_x1[(size_t)NMAX*LL*CC];
__device__ float g_rad[(size_t)EMAX*64];
__device__ float g_logits[(size_t)EMAX*8];
__device__ float g_segmax[NMAX*8];
__device__ float g_denom[NMAX*8];
__device__ float g_agg[(size_t)NMAX*LL*128];
__device__ float g_x2[(size_t)NMAX*LL*CC];
__device__ float g_gg[(size_t)NMAX*GG*128];

__device__ __forceinline__ float sigmoidf_(float x){ return 1.f/(1.f+__expf(-x)); }

__device__ __forceinline__ void atomicMaxF(float* addr, float v){
    if (v >= 0.f) atomicMax((int*)addr, __float_as_int(v));
    else          atomicMin((unsigned int*)addr, __float_as_uint(v));
}

// ---------------- row-tiled small-GEMM helpers (broadcast-LDS + coalesced-LDG) ----------------
// A smem [rows][128], W [128][64] row-major (k fast over threads), out smem [rows][64]
template<int R>
__device__ __forceinline__ void mm_rows_h(const float* __restrict__ sA,
                                          const float* __restrict__ W,
                                          float* __restrict__ sOut,
                                          int base, int c, float scale){
    float acc[R];
    #pragma unroll
    for (int rr=0; rr<R; rr++) acc[rr] = 0.f;
    #pragma unroll 8
    for (int k=0; k<128; k++){
        float w = __ldg(&W[k*64+c]);
        #pragma unroll
        for (int rr=0; rr<R; rr++) acc[rr] += sA[(base+rr)*128+k]*w;
    }
    #pragma unroll
    for (int rr=0; rr<R; rr++) sOut[(base+rr)*64+c] = acc[rr]*scale;
}

// A smem [rows][64], W [64][128], out smem [rows][128]
template<int R>
__device__ __forceinline__ void mm_rows_v(const float* __restrict__ sA,
                                          const float* __restrict__ W,
                                          float* __restrict__ sOut,
                                          int base, int c, float scale){
    float acc[R];
    #pragma unroll
    for (int rr=0; rr<R; rr++) acc[rr] = 0.f;
    #pragma unroll 8
    for (int k=0; k<64; k++){
        float w = __ldg(&W[k*128+c]);
        #pragma unroll
        for (int rr=0; rr<R; rr++) acc[rr] += sA[(base+rr)*64+k]*w;
    }
    #pragma unroll
    for (int rr=0; rr<R; rr++) sOut[(base+rr)*128+c] = acc[rr]*scale;
}

// A smem [rows][128], W [128][64], out global [rows][64] + residual
template<int R>
__device__ __forceinline__ void mm_rows_out64(const float* __restrict__ sA,
                                              const float* __restrict__ W,
                                              const float* __restrict__ res,
                                              float* __restrict__ outp,
                                              int base, int c){
    float acc[R];
    #pragma unroll
    for (int rr=0; rr<R; rr++) acc[rr] = 0.f;
    #pragma unroll 8
    for (int k=0; k<128; k++){
        float w = __ldg(&W[k*64+c]);
        #pragma unroll
        for (int rr=0; rr<R; rr++) acc[rr] += sA[(base+rr)*128+k]*w;
    }
    #pragma unroll
    for (int rr=0; rr<R; rr++)
        outp[(base+rr)*64+c] = acc[rr] + res[(base+rr)*64+c];
}

// A smem [rows][64], W [64][128], out smem [rows][128]
template<int R>
__device__ __forceinline__ void mm_rows_ff1(const float* __restrict__ sA,
                                            const float* __restrict__ W,
                                            float* __restrict__ sOut,
                                            int base, int f){
    float acc[R];
    #pragma unroll
    for (int rr=0; rr<R; rr++) acc[rr] = 0.f;
    #pragma unroll 8
    for (int k=0; k<64; k++){
        float w = __ldg(&W[k*128+f]);
        #pragma unroll
        for (int rr=0; rr<R; rr++) acc[rr] += sA[(base+rr)*64+k]*w;
    }
    #pragma unroll
    for (int rr=0; rr<R; rr++) sOut[(base+rr)*128+f] = acc[rr];
}

// ---------------- kernels ----------------

__global__ void k_init(int N){
    int i = blockIdx.x*blockDim.x + threadIdx.x;
    int stride = gridDim.x*blockDim.x;
    int tot = N*LL*128;
    for (int idx=i; idx<tot; idx+=stride) g_agg[idx] = 0.f;
    if (i < N*8){ g_denom[i] = 0.f; g_segmax[i] = -1e30f; }
}

__global__ void k_norm1(const float* __restrict__ nf, const float* __restrict__ w, int N){
    int n = blockIdx.x; int t = threadIdx.x;
    __shared__ float ssq[5], sinv[5];
    if (t < 5) ssq[t] = 0.f;
    __syncthreads();
    const float* src = nf + (size_t)n*1600;
    #pragma unroll
    for (int d=0; d<5; d++){
        int b = d*d*64, cnt = (2*d+1)*64;
        float a = 0.f;
        for (int idx=t; idx<cnt; idx+=128){ float v = src[b+idx]; a += v*v; }
        #pragma unroll
        for (int off=16; off>0; off>>=1) a += __shfl_down_sync(0xffffffffu, a, off);
        if ((t & 31) == 0) atomicAdd(&ssq[d], a);
    }
    __syncthreads();
    if (t < 5) sinv[t] = rsqrtf(ssq[t] / ((2.f*t+1.f)*64.f) + EPSF);
    __syncthreads();
    float* dst = g_x1 + (size_t)n*1600;
    for (int idx=t; idx<1600; idx+=128){
        int l = idx>>6, c = idx&63;
        int d = c_deg[l];
        dst[idx] = src[idx] * sinv[d] * __ldg(&w[d*64+c]);
    }
}

// 2 edges per 128-thread block; each 64-thread sub-block runs all stages full-width.
// Weight access: k-loop scalar broadcast over smem activations, coalesced LDG over c.
__global__ __launch_bounds__(128)
void k_edge_logits(const float* __restrict__ dist, const int* __restrict__ species,
                   const int* __restrict__ senders, const int* __restrict__ receivers,
                   const float* __restrict__ wigner,
                   const float* __restrict__ W_edge, const float* __restrict__ emb_src,
                   const float* __restrict__ emb_dst,
                   const float* __restrict__ W_r1, const float* __restrict__ b_r1,
                   const float* __restrict__ W_r2, const float* __restrict__ b_r2,
                   const float* __restrict__ W_msg, const float* __restrict__ W_alpha,
                   const float* __restrict__ alpha_vec, int E){
    int t = threadIdx.x;
    int sub = t >> 6;
    int c = t & 63;
    int e = blockIdx.x*2 + sub;
    bool valid = (e < E);
    if (!valid) e = E-1;

    __shared__ float sdist[2][64], se[2][64], sr1[2][64], sm0[2][128], sh0[2][64];

    int s = senders[e], r = receivers[e];
    int sps = species[s], spr = species[r];
    sdist[sub][c] = dist[(size_t)e*64+c];
    __syncthreads();
    // stage 1: e = dist @ W_edge + embeddings
    {
        float acc = __ldg(&emb_src[sps*64+c]) + __ldg(&emb_dst[spr*64+c]);
        #pragma unroll 8
        for (int k=0; k<64; k++) acc += sdist[sub][k]*__ldg(&W_edge[k*64+c]);
        se[sub][c] = acc;
    }
    __syncthreads();
    // stage 2: silu(e @ W_r1 + b1)
    {
        float acc = __ldg(&b_r1[c]);
        #pragma unroll 8
        for (int k=0; k<64; k++) acc += se[sub][k]*__ldg(&W_r1[k*64+c]);
        sr1[sub][c] = acc * sigmoidf_(acc);
    }
    __syncthreads();
    // stage 3: rad = sr1 @ W_r2 + b2
    float rad;
    {
        float acc = __ldg(&b_r2[c]);
        #pragma unroll 8
        for (int k=0; k<64; k++) acc += sr1[sub][k]*__ldg(&W_r2[k*64+c]);
        rad = acc;
        g_rad[(size_t)e*64+c] = acc;
    }
    // m0: row 0 of rotated concat message (each thread: both halves at column c)
    {
        const float* wg = wigner + (size_t)e*625;
        const float* xs = g_x1 + (size_t)s*1600 + c;
        const float* xr = g_x1 + (size_t)r*1600 + c;
        float a0=0.f, a1=0.f;
        #pragma unroll
        for (int j=0; j<25; j++){
            float w = __ldg(&wg[j]);
            a0 = fmaf(w, xs[j*64], a0);
            a1 = fmaf(w, xr[j*64], a1);
        }
        sm0[sub][c] = a0; sm0[sub][64+c] = a1;
    }
    __syncthreads();
    // h0 = (m0 @ W_msg[deg0]) * rad, gated
    {
        float acc = 0.f;
        #pragma unroll 8
        for (int k=0; k<128; k++) acc += sm0[sub][k]*__ldg(&W_msg[k*64+c]);
        acc *= rad;
        sh0[sub][c] = acc * sigmoidf_(acc);
    }
    __syncthreads();
    // alpha: two outputs per thread (o=c, o=c+64), then 16-lane head reduction
    {
        float a0=0.f, a1=0.f;
        #pragma unroll 8
        for (int k=0; k<64; k++){
            float hv = sh0[sub][k];
            a0 = fmaf(hv, __ldg(&W_alpha[k*128+c]),    a0);
            a1 = fmaf(hv, __ldg(&W_alpha[k*128+c+64]), a1);
        }
        a0 = (a0 > 0.f) ? a0 : 0.2f*a0;
        a1 = (a1 > 0.f) ? a1 : 0.2f*a1;
        float p0 = a0 * __ldg(&alpha_vec[c]);
        float p1 = a1 * __ldg(&alpha_vec[c+64]);
        #pragma unroll
        for (int off=8; off>0; off>>=1){
            p0 += __shfl_down_sync(0xffffffffu, p0, off);
            p1 += __shfl_down_sync(0xffffffffu, p1, off);
        }
        if (((t & 15) == 0) && valid){
            g_logits[(size_t)e*8 + (c>>4)]     = p0;
            g_logits[(size_t)e*8 + 4 + (c>>4)] = p1;
        }
    }
}

__global__ void k_segmax(const int* __restrict__ receivers, int E){
    int i = blockIdx.x*blockDim.x + threadIdx.x;
    if (i >= E*8) return;
    int e = i>>3, hh = i&7;
    atomicMaxF(&g_segmax[receivers[e]*8+hh], g_logits[i]);
}

__global__ void k_denom(const int* __restrict__ receivers, int E){
    int i = blockIdx.x*blockDim.x + threadIdx.x;
    if (i >= E*8) return;
    int e = i>>3, hh = i&7;
    int r = receivers[e];
    atomicAdd(&g_denom[r*8+hh], __expf(g_logits[i] - g_segmax[r*8+hh]));
}

// main edge kernel: gather -> rotate -> W_msg*rad*gate -> W_val*attn -> rotate back -> bulk reduce
__global__ __launch_bounds__(128)
void k_edge_main(const int* __restrict__ senders, const int* __restrict__ receivers,
                 const float* __restrict__ wigner,
                 const float* __restrict__ W_msg, const float* __restrict__ W_val, int E){
    int e = blockIdx.x; int t = threadIdx.x;
    __shared__ float swig[625];
    __shared__ __align__(16) float smrot[LL*128];   // msgrot, later rotated-back v (bulk-red source)
    __shared__ float sh[LL*64];
    __shared__ float sv[LL*128];
    __shared__ float srad[64], ssig[64], sattn[8];

    int s = senders[e], r = receivers[e];
    for (int i=t; i<625; i+=128) swig[i] = wigner[(size_t)e*625+i];
    if (t < 64) srad[t] = g_rad[(size_t)e*64+t];
    if (t < 8){
        float lg = g_logits[(size_t)e*8+t];
        sattn[t] = __expf(lg - g_segmax[r*8+t]) / (g_denom[r*8+t] + EPSF);
    }
    __syncthreads();

    // gather my column of concat(x[s], x[r]) and rotate
    float mc[LL];
    {
        const float* xb = (t < 64) ? (g_x1 + (size_t)s*1600 + t)
                                   : (g_x1 + (size_t)r*1600 + (t-64));
        #pragma unroll
        for (int j=0; j<LL; j++) mc[j] = xb[j*64];
    }
    #pragma unroll 1
    for (int i=0; i<LL; i++){
        float acc = 0.f;
        #pragma unroll
        for (int j=0; j<LL; j++) acc += swig[i*25+j]*mc[j];
        smrot[i*128+t] = acc;
    }
    __syncthreads();

    // h0 (degree 0) + gate
    if (t < 64){
        float acc = 0.f;
        #pragma unroll 8
        for (int k=0; k<128; k++) acc += smrot[k]*__ldg(&W_msg[k*64+t]);
        acc *= srad[t];
        float sg = sigmoidf_(acc);
        ssig[t] = sg;
        sh[t] = acc*sg;
    }
    __syncthreads();

    // remaining degrees, split across the two half-blocks (12 rows each)
    {
        int c = t & 63;
        float scale = srad[c]*ssig[c];
        if (t < 64){
            mm_rows_h<3>(smrot, W_msg + 1*8192, sh, 1,  c, scale);  // degree 1
            mm_rows_h<9>(smrot, W_msg + 4*8192, sh, 16, c, scale);  // degree 4
        } else {
            mm_rows_h<5>(smrot, W_msg + 2*8192, sh, 4,  c, scale);  // degree 2
            mm_rows_h<7>(smrot, W_msg + 3*8192, sh, 9,  c, scale);  // degree 3
        }
    }
    __syncthreads();

    // v = h @ W_val[deg], scaled by per-head attention (writes column t of sv)
    {
        float attn = sattn[t>>4];
        mm_rows_v<1>(sh, W_val + 0*8192, sv, 0,  t, attn);
        mm_rows_v<3>(sh, W_val + 1*8192, sv, 1,  t, attn);
        mm_rows_v<5>(sh, W_val + 2*8192, sv, 4,  t, attn);
        mm_rows_v<7>(sh, W_val + 3*8192, sv, 9,  t, attn);
        mm_rows_v<9>(sh, W_val + 4*8192, sv, 16, t, attn);
    }
    // rotate back with wigner^T: column t of sv -> column t of smrot (column-private, no sync)
    #pragma unroll
    for (int j=0; j<LL; j++) mc[j] = sv[j*128+t];
    #pragma unroll 1
    for (int i=0; i<LL; i++){
        float acc = 0.f;
        #pragma unroll
        for (int j=0; j<LL; j++) acc += swig[j*25+i]*mc[j];
        smrot[i*128+t] = acc;
    }
    __syncthreads();

    // one bulk reduce-add of the whole 25x128 tile into g_agg[r]
    if (t == 0){
        asm volatile("fence.proxy.async.shared::cta;" ::: "memory");
        float* dst = g_agg + (size_t)r*3200;
        uint32_t sptr;
        asm("{ .reg .u64 tt; cvta.to.shared.u64 tt, %1; cvt.u32.u64 %0, tt; }"
            : "=r"(sptr) : "l"(smrot));
        asm volatile("cp.reduce.async.bulk.global.shared::cta.bulk_group.add.f32 [%0], [%1], %2;"
                     :: "l"(dst), "r"(sptr), "r"(12800) : "memory");
        asm volatile("cp.async.bulk.commit_group;" ::: "memory");
        asm volatile("cp.async.bulk.wait_group 0;" ::: "memory");
    }
    __syncthreads();
}

// x2 = agg @ W_out[deg] + node_feats
__global__ __launch_bounds__(128)
void k_wout(const float* __restrict__ nf, const float* __restrict__ W_out, int N){
    int n = blockIdx.x; int t = threadIdx.x;
    __shared__ __align__(16) float sagg[LL*128];
    {
        const float4* src = (const float4*)(g_agg + (size_t)n*3200);
        float4* dst4 = (float4*)sagg;
        for (int i=t; i<800; i+=128) dst4[i] = src[i];
    }
    __syncthreads();
    int c = t & 63;
    const float* res = nf + (size_t)n*1600;
    float* outp = g_x2 + (size_t)n*1600;
    if (t < 64){
        mm_rows_out64<1>(sagg, W_out + 0*8192, res, outp, 0,  c);
        mm_rows_out64<3>(sagg, W_out + 1*8192, res, outp, 1,  c);
        mm_rows_out64<9>(sagg, W_out + 4*8192, res, outp, 16, c);
    } else {
        mm_rows_out64<5>(sagg, W_out + 2*8192, res, outp, 4,  c);
        mm_rows_out64<7>(sagg, W_out + 3*8192, res, outp, 9,  c);
    }
}

// FFN part A: norm2 -> ff1 -> to_grid -> W_grid+silu -> g_gg
__global__ __launch_bounds__(128)
void k_ffn_a(const float* __restrict__ norm2w, const float* __restrict__ W_ff1,
             const float* __restrict__ to_grid, const float* __restrict__ W_grid,
             const float* __restrict__ b_grid, int N){
    int n = blockIdx.x; int t = threadIdx.x;
    __shared__ float sx[LL*64];
    __shared__ float st1[LL*128];
    __shared__ float sg[GG*128];
    __shared__ float stg[GG*LL];
    __shared__ float ssq[5], sinv[5];

    if (t < 5) ssq[t] = 0.f;
    for (int i=t; i<GG*LL; i+=128) stg[i] = __ldg(&to_grid[i]);
    __syncthreads();

    const float* xb = g_x2 + (size_t)n*1600;
    #pragma unroll
    for (int d=0; d<5; d++){
        int b = d*d*64, cnt = (2*d+1)*64;
        float a = 0.f;
        for (int idx=t; idx<cnt; idx+=128){ float v = xb[b+idx]; sx[b+idx] = v; a += v*v; }
        #pragma unroll
        for (int off=16; off>0; off>>=1) a += __shfl_down_sync(0xffffffffu, a, off);
        if ((t & 31) == 0) atomicAdd(&ssq[d], a);
    }
    __syncthreads();
    if (t < 5) sinv[t] = rsqrtf(ssq[t] / ((2.f*t+1.f)*64.f) + EPSF);
    __syncthreads();
    for (int idx=t; idx<1600; idx+=128){
        int l = idx>>6, c = idx&63;
        int d = c_deg[l];
        sx[idx] *= sinv[d] * __ldg(&norm2w[d*64+c]);
    }
    __syncthreads();

    // ff1: [25,64] -> [25,128]
    mm_rows_ff1<1>(sx, W_ff1 + 0*8192, st1, 0,  t);
    mm_rows_ff1<3>(sx, W_ff1 + 1*8192, st1, 1,  t);
    mm_rows_ff1<5>(sx, W_ff1 + 2*8192, st1, 4,  t);
    mm_rows_ff1<7>(sx, W_ff1 + 3*8192, st1, 9,  t);
    mm_rows_ff1<9>(sx, W_ff1 + 4*8192, st1, 16, t);
    __syncthreads();

    // to_grid: g[p][t] = sum_l tg[p][l] * t1[l][t]
    #pragma unroll 1
    for (int p=0; p<GG; p++){
        float acc = 0.f;
        #pragma unroll
        for (int l=0; l<LL; l++) acc += stg[p*25+l]*st1[l*128+t];
        sg[p*128+t] = acc;
    }
    __syncthreads();

    // W_grid + silu, 5-row tiles (45 = 9*5)
    float bg = __ldg(&b_grid[t]);
    #pragma unroll 1
    for (int pt=0; pt<9; pt++){
        float acc[5] = {0.f,0.f,0.f,0.f,0.f};
        #pragma unroll 4
        for (int k=0; k<128; k++){
            float w = __ldg(&W_grid[k*128+t]);
            #pragma unroll
            for (int rr=0; rr<5; rr++) acc[rr] += sg[(pt*5+rr)*128+k]*w;
        }
        #pragma unroll
        for (int rr=0; rr<5; rr++){
            float z = acc[rr] + bg;
            g_gg[((size_t)n*GG + pt*5+rr)*128 + t] = z * sigmoidf_(z);
        }
    }
}

// FFN part B: from_grid -> ff2 + residual -> out
__global__ __launch_bounds__(128)
void k_ffn_b(const float* __restrict__ from_grid, const float* __restrict__ W_ff2,
             float* __restrict__ out, int N){
    int n = blockIdx.x; int t = threadIdx.x;
    __shared__ float sgg[GG*128];
    __shared__ float sfg[LL*GG];
    __shared__ float sy2[LL*128];

    for (int i=t; i<GG*128; i+=128) sgg[i] = g_gg[(size_t)n*GG*128 + i];
    for (int i=t; i<LL*GG; i+=128) sfg[i] = __ldg(&from_grid[i]);
    __syncthreads();

    #pragma unroll 1
    for (int l=0; l<LL; l++){
        float acc = 0.f;
        #pragma unroll
        for (int p=0; p<GG; p++) acc += sfg[l*45+p]*sgg[p*128+t];
        sy2[l*128+t] = acc;
    }
    __syncthreads();

    int c = t & 63;
    const float* res = g_x2 + (size_t)n*1600;
    float* outp = out + (size_t)n*1600;
    if (t < 64){
        mm_rows_out64<1>(sy2, W_ff2 + 0*8192, res, outp, 0,  c);
        mm_rows_out64<3>(sy2, W_ff2 + 1*8192, res, outp, 1,  c);
        mm_rows_out64<9>(sy2, W_ff2 + 4*8192, res, outp, 16, c);
    } else {
        mm_rows_out64<5>(sy2, W_ff2 + 2*8192, res, outp, 4,  c);
        mm_rows_out64<7>(sy2, W_ff2 + 3*8192, res, outp, 9,  c);
    }
}

// ---------------- host launcher ----------------
extern "C" void kernel_launch(void* const* d_in, const int* in_sizes, int n_in,
                              void* d_out, int out_size){
    int p = (in_sizes[6] <= 4) ? 7 : 6;

    const float* node_feats = (const float*)d_in[0];
    const int*   species    = (const int*)  d_in[1];
    const float* edge_dist  = (const float*)d_in[2];
    const int*   senders    = (const int*)  d_in[3];
    const int*   receivers  = (const int*)  d_in[4];
    const float* wigner     = (const float*)d_in[5];
    const float* norm1_w    = (const float*)d_in[p+0];
    const float* norm2_w    = (const float*)d_in[p+1];
    const float* W_edge     = (const float*)d_in[p+2];
    const float* emb_src    = (const float*)d_in[p+3];
    const float* emb_dst    = (const float*)d_in[p+4];
    const float* W_r1       = (const float*)d_in[p+5];
    const float* b_r1       = (const float*)d_in[p+6];
    const float* W_r2       = (const float*)d_in[p+7];
    const float* b_r2       = (const float*)d_in[p+8];
    const float* W_msg      = (const float*)d_in[p+9];
    const float* W_alpha    = (const float*)d_in[p+10];
    const float* alpha_vec  = (const float*)d_in[p+11];
    const float* W_val      = (const float*)d_in[p+12];
    const float* W_out      = (const float*)d_in[p+13];
    const float* W_ff1      = (const float*)d_in[p+14];
    const float* to_grid    = (const float*)d_in[p+15];
    const float* from_grid  = (const float*)d_in[p+16];
    const float* W_grid     = (const float*)d_in[p+17];
    const float* b_grid     = (const float*)d_in[p+18];
    const float* W_ff2      = (const float*)d_in[p+19];

    int N = in_sizes[0] / (LL*CC);
    int E = in_sizes[3];
    if (N > NMAX) N = NMAX;
    if (E > EMAX) E = EMAX;

    k_init<<<2048, 256>>>(N);
    k_norm1<<<N, 128>>>(node_feats, norm1_w, N);
    k_edge_logits<<<(E+1)/2, 128>>>(edge_dist, species, senders, receivers, wigner,
                                    W_edge, emb_src, emb_dst, W_r1, b_r1, W_r2, b_r2,
                                    W_msg, W_alpha, alpha_vec, E);
    int segthreads = 256;
    int segblocks = (E*8 + segthreads - 1) / segthreads;
    k_segmax<<<segblocks, segthreads>>>(receivers, E);
    k_denom<<<segblocks, segthreads>>>(receivers, E);
    k_edge_main<<<E, 128>>>(senders, receivers, wigner, W_msg, W_val, E);
    k_wout<<<N, 128>>>(node_feats, W_out, N);
    k_ffn_a<<<N, 128>>>(norm2_w, W_ff1, to_grid, W_grid, b_grid, N);
    k_ffn_b<<<N, 128>>>(from_grid, W_ff2, (float*)d_out, N);
}

// round 6
// speedup vs baseline: 2.3795x; 1.4109x over previous
#include <cuda_runtime.h>
#include <math.h>
#include <stdint.h>

#define LL 25
#define CC 64
#define NMAX 4096
#define EMAX 32768
#define GG 45
#define EPSF 1e-6f

__constant__ int c_deg[25] = {0,1,1,1,2,2,2,2,2,3,3,3,3,3,3,3,4,4,4,4,4,4,4,4,4};

// ---------------- scratch ----------------
__device__ float g_x1[(size_t)NMAX*LL*CC];
__device__ float g_rad[(size_t)EMAX*64];
__device__ float g_logits[(size_t)EMAX*8];
__device__ float g_segmax[NMAX*8];
__device__ float g_denom[NMAX*8];
__device__ float g_agg[(size_t)NMAX*LL*128];
__device__ float g_x2[(size_t)NMAX*LL*CC];
__device__ float g_gg[(size_t)NMAX*GG*128];

__device__ __forceinline__ float sigmoidf_(float x){ return 1.f/(1.f+__expf(-x)); }

__device__ __forceinline__ void atomicMaxF(float* addr, float v){
    if (v >= 0.f) atomicMax((int*)addr, __float_as_int(v));
    else          atomicMin((unsigned int*)addr, __float_as_uint(v));
}

// ---------------- vectorized-LDS small-GEMM helpers ----------------
// Pattern: weights stay in original layout (coalesced scalar LDG over output col),
// activations read as broadcast LDS.128 (4 k-values per instruction).

// A smem [rows][128], W [128][64], out smem [rows][64], scaled
template<int R>
__device__ __forceinline__ void mm4_h(const float* __restrict__ sA,
                                      const float* __restrict__ W,
                                      float* __restrict__ sOut,
                                      int base, int c, float scale){
    float acc[R];
    #pragma unroll
    for (int rr=0; rr<R; rr++) acc[rr] = 0.f;
    #pragma unroll 4
    for (int q=0; q<32; q++){
        float w0 = __ldg(&W[(4*q+0)*64+c]);
        float w1 = __ldg(&W[(4*q+1)*64+c]);
        float w2 = __ldg(&W[(4*q+2)*64+c]);
        float w3 = __ldg(&W[(4*q+3)*64+c]);
        #pragma unroll
        for (int rr=0; rr<R; rr++){
            float4 a = *(const float4*)&sA[(base+rr)*128 + 4*q];
            acc[rr] = fmaf(a.x,w0,fmaf(a.y,w1,fmaf(a.z,w2,fmaf(a.w,w3,acc[rr]))));
        }
    }
    #pragma unroll
    for (int rr=0; rr<R; rr++) sOut[(base+rr)*64+c] = acc[rr]*scale;
}

// A smem [rows][64], W [64][128], out smem [rows][128], scaled
template<int R>
__device__ __forceinline__ void mm4_v(const float* __restrict__ sA,
                                      const float* __restrict__ W,
                                      float* __restrict__ sOut,
                                      int base, int c, float scale){
    float acc[R];
    #pragma unroll
    for (int rr=0; rr<R; rr++) acc[rr] = 0.f;
    #pragma unroll 4
    for (int q=0; q<16; q++){
        float w0 = __ldg(&W[(4*q+0)*128+c]);
        float w1 = __ldg(&W[(4*q+1)*128+c]);
        float w2 = __ldg(&W[(4*q+2)*128+c]);
        float w3 = __ldg(&W[(4*q+3)*128+c]);
        #pragma unroll
        for (int rr=0; rr<R; rr++){
            float4 a = *(const float4*)&sA[(base+rr)*64 + 4*q];
            acc[rr] = fmaf(a.x,w0,fmaf(a.y,w1,fmaf(a.z,w2,fmaf(a.w,w3,acc[rr]))));
        }
    }
    #pragma unroll
    for (int rr=0; rr<R; rr++) sOut[(base+rr)*128+c] = acc[rr]*scale;
}

// A smem [rows][128], W [128][64], out global [rows][64] + residual
template<int R>
__device__ __forceinline__ void mm4_out(const float* __restrict__ sA,
                                        const float* __restrict__ W,
                                        const float* __restrict__ res,
                                        float* __restrict__ outp,
                                        int base, int c){
    float acc[R];
    #pragma unroll
    for (int rr=0; rr<R; rr++) acc[rr] = 0.f;
    #pragma unroll 4
    for (int q=0; q<32; q++){
        float w0 = __ldg(&W[(4*q+0)*64+c]);
        float w1 = __ldg(&W[(4*q+1)*64+c]);
        float w2 = __ldg(&W[(4*q+2)*64+c]);
        float w3 = __ldg(&W[(4*q+3)*64+c]);
        #pragma unroll
        for (int rr=0; rr<R; rr++){
            float4 a = *(const float4*)&sA[(base+rr)*128 + 4*q];
            acc[rr] = fmaf(a.x,w0,fmaf(a.y,w1,fmaf(a.z,w2,fmaf(a.w,w3,acc[rr]))));
        }
    }
    #pragma unroll
    for (int rr=0; rr<R; rr++)
        outp[(base+rr)*64+c] = acc[rr] + res[(base+rr)*64+c];
}

// A smem [rows][64], W [64][128], out regs t1[base..base+R)
template<int R>
__device__ __forceinline__ void ff14_rows(const float* __restrict__ sA,
                                          const float* __restrict__ W,
                                          float* __restrict__ t1,
                                          int base, int f){
    float acc[R];
    #pragma unroll
    for (int rr=0; rr<R; rr++) acc[rr] = 0.f;
    #pragma unroll 4
    for (int q=0; q<16; q++){
        float w0 = __ldg(&W[(4*q+0)*128+f]);
        float w1 = __ldg(&W[(4*q+1)*128+f]);
        float w2 = __ldg(&W[(4*q+2)*128+f]);
        float w3 = __ldg(&W[(4*q+3)*128+f]);
        #pragma unroll
        for (int rr=0; rr<R; rr++){
            float4 a = *(const float4*)&sA[(base+rr)*64 + 4*q];
            acc[rr] = fmaf(a.x,w0,fmaf(a.y,w1,fmaf(a.z,w2,fmaf(a.w,w3,acc[rr]))));
        }
    }
    #pragma unroll
    for (int rr=0; rr<R; rr++) t1[base+rr] = acc[rr];
}

// ---------------- kernels ----------------

__global__ void k_init(int N){
    int i = blockIdx.x*blockDim.x + threadIdx.x;
    int stride = gridDim.x*blockDim.x;
    int tot = N*LL*128;
    for (int idx=i; idx<tot; idx+=stride) g_agg[idx] = 0.f;
    if (i < N*8){ g_denom[i] = 0.f; g_segmax[i] = -1e30f; }
}

__global__ void k_norm1(const float* __restrict__ nf, const float* __restrict__ w, int N){
    int n = blockIdx.x; int t = threadIdx.x;
    __shared__ float ssq[5], sinv[5];
    if (t < 5) ssq[t] = 0.f;
    __syncthreads();
    const float* src = nf + (size_t)n*1600;
    #pragma unroll
    for (int d=0; d<5; d++){
        int b = d*d*64, cnt = (2*d+1)*64;
        float a = 0.f;
        for (int idx=t; idx<cnt; idx+=128){ float v = src[b+idx]; a += v*v; }
        #pragma unroll
        for (int off=16; off>0; off>>=1) a += __shfl_down_sync(0xffffffffu, a, off);
        if ((t & 31) == 0) atomicAdd(&ssq[d], a);
    }
    __syncthreads();
    if (t < 5) sinv[t] = rsqrtf(ssq[t] / ((2.f*t+1.f)*64.f) + EPSF);
    __syncthreads();
    float* dst = g_x1 + (size_t)n*1600;
    for (int idx=t; idx<1600; idx+=128){
        int l = idx>>6, c = idx&63;
        int d = c_deg[l];
        dst[idx] = src[idx] * sinv[d] * __ldg(&w[d*64+c]);
    }
}

// 2 edges per 128-thread block; each 64-thread sub-block runs all stages full-width.
__global__ __launch_bounds__(128)
void k_edge_logits(const float* __restrict__ dist, const int* __restrict__ species,
                   const int* __restrict__ senders, const int* __restrict__ receivers,
                   const float* __restrict__ wigner,
                   const float* __restrict__ W_edge, const float* __restrict__ emb_src,
                   const float* __restrict__ emb_dst,
                   const float* __restrict__ W_r1, const float* __restrict__ b_r1,
                   const float* __restrict__ W_r2, const float* __restrict__ b_r2,
                   const float* __restrict__ W_msg, const float* __restrict__ W_alpha,
                   const float* __restrict__ alpha_vec, int E){
    int t = threadIdx.x;
    int sub = t >> 6;
    int c = t & 63;
    int e = blockIdx.x*2 + sub;
    bool valid = (e < E);
    if (!valid) e = E-1;

    __shared__ __align__(16) float sdist[2][64], se[2][64], sr1[2][64], sm0[2][128], sh0[2][64];

    int s = senders[e], r = receivers[e];
    int sps = species[s], spr = species[r];
    sdist[sub][c] = dist[(size_t)e*64+c];
    __syncthreads();
    // stage 1: e = dist @ W_edge + embeddings
    {
        float acc = __ldg(&emb_src[sps*64+c]) + __ldg(&emb_dst[spr*64+c]);
        #pragma unroll 4
        for (int q=0; q<16; q++){
            float w0 = __ldg(&W_edge[(4*q+0)*64+c]);
            float w1 = __ldg(&W_edge[(4*q+1)*64+c]);
            float w2 = __ldg(&W_edge[(4*q+2)*64+c]);
            float w3 = __ldg(&W_edge[(4*q+3)*64+c]);
            float4 a = *(const float4*)&sdist[sub][4*q];
            acc = fmaf(a.x,w0,fmaf(a.y,w1,fmaf(a.z,w2,fmaf(a.w,w3,acc))));
        }
        se[sub][c] = acc;
    }
    __syncthreads();
    // stage 2: silu(e @ W_r1 + b1)
    {
        float acc = __ldg(&b_r1[c]);
        #pragma unroll 4
        for (int q=0; q<16; q++){
            float w0 = __ldg(&W_r1[(4*q+0)*64+c]);
            float w1 = __ldg(&W_r1[(4*q+1)*64+c]);
            float w2 = __ldg(&W_r1[(4*q+2)*64+c]);
            float w3 = __ldg(&W_r1[(4*q+3)*64+c]);
            float4 a = *(const float4*)&se[sub][4*q];
            acc = fmaf(a.x,w0,fmaf(a.y,w1,fmaf(a.z,w2,fmaf(a.w,w3,acc))));
        }
        sr1[sub][c] = acc * sigmoidf_(acc);
    }
    __syncthreads();
    // stage 3: rad = sr1 @ W_r2 + b2
    float rad;
    {
        float acc = __ldg(&b_r2[c]);
        #pragma unroll 4
        for (int q=0; q<16; q++){
            float w0 = __ldg(&W_r2[(4*q+0)*64+c]);
            float w1 = __ldg(&W_r2[(4*q+1)*64+c]);
            float w2 = __ldg(&W_r2[(4*q+2)*64+c]);
            float w3 = __ldg(&W_r2[(4*q+3)*64+c]);
            float4 a = *(const float4*)&sr1[sub][4*q];
            acc = fmaf(a.x,w0,fmaf(a.y,w1,fmaf(a.z,w2,fmaf(a.w,w3,acc))));
        }
        rad = acc;
        g_rad[(size_t)e*64+c] = acc;
    }
    // m0: row 0 of rotated concat message (each thread: both halves at column c)
    {
        const float* wg = wigner + (size_t)e*625;
        const float* xs = g_x1 + (size_t)s*1600 + c;
        const float* xr = g_x1 + (size_t)r*1600 + c;
        float a0=0.f, a1=0.f;
        #pragma unroll
        for (int j=0; j<25; j++){
            float w = __ldg(&wg[j]);
            a0 = fmaf(w, xs[j*64], a0);
            a1 = fmaf(w, xr[j*64], a1);
        }
        sm0[sub][c] = a0; sm0[sub][64+c] = a1;
    }
    __syncthreads();
    // h0 = (m0 @ W_msg[deg0]) * rad, gated
    {
        float acc = 0.f;
        #pragma unroll 4
        for (int q=0; q<32; q++){
            float w0 = __ldg(&W_msg[(4*q+0)*64+c]);
            float w1 = __ldg(&W_msg[(4*q+1)*64+c]);
            float w2 = __ldg(&W_msg[(4*q+2)*64+c]);
            float w3 = __ldg(&W_msg[(4*q+3)*64+c]);
            float4 a = *(const float4*)&sm0[sub][4*q];
            acc = fmaf(a.x,w0,fmaf(a.y,w1,fmaf(a.z,w2,fmaf(a.w,w3,acc))));
        }
        acc *= rad;
        sh0[sub][c] = acc * sigmoidf_(acc);
    }
    __syncthreads();
    // alpha: two outputs per thread (o=c, o=c+64), then 16-lane head reduction
    {
        float a0=0.f, a1=0.f;
        #pragma unroll 4
        for (int q=0; q<16; q++){
            float4 hv = *(const float4*)&sh0[sub][4*q];
            #pragma unroll
            for (int i=0; i<4; i++){
                float h = (i==0)?hv.x:(i==1)?hv.y:(i==2)?hv.z:hv.w;
                a0 = fmaf(h, __ldg(&W_alpha[(4*q+i)*128+c]),    a0);
                a1 = fmaf(h, __ldg(&W_alpha[(4*q+i)*128+c+64]), a1);
            }
        }
        a0 = (a0 > 0.f) ? a0 : 0.2f*a0;
        a1 = (a1 > 0.f) ? a1 : 0.2f*a1;
        float p0 = a0 * __ldg(&alpha_vec[c]);
        float p1 = a1 * __ldg(&alpha_vec[c+64]);
        #pragma unroll
        for (int off=8; off>0; off>>=1){
            p0 += __shfl_down_sync(0xffffffffu, p0, off);
            p1 += __shfl_down_sync(0xffffffffu, p1, off);
        }
        if (((t & 15) == 0) && valid){
            g_logits[(size_t)e*8 + (c>>4)]     = p0;
            g_logits[(size_t)e*8 + 4 + (c>>4)] = p1;
        }
    }
}

__global__ void k_segmax(const int* __restrict__ receivers, int E){
    int i = blockIdx.x*blockDim.x + threadIdx.x;
    if (i >= E*8) return;
    int e = i>>3, hh = i&7;
    atomicMaxF(&g_segmax[receivers[e]*8+hh], g_logits[i]);
}

__global__ void k_denom(const int* __restrict__ receivers, int E){
    int i = blockIdx.x*blockDim.x + threadIdx.x;
    if (i >= E*8) return;
    int e = i>>3, hh = i&7;
    int r = receivers[e];
    atomicAdd(&g_denom[r*8+hh], __expf(g_logits[i] - g_segmax[r*8+hh]));
}

// main edge kernel
__global__ __launch_bounds__(128)
void k_edge_main(const int* __restrict__ senders, const int* __restrict__ receivers,
                 const float* __restrict__ wigner,
                 const float* __restrict__ W_msg, const float* __restrict__ W_val, int E){
    int e = blockIdx.x; int t = threadIdx.x;
    __shared__ __align__(16) float swig[25*28];    // padded rows (112B = 7x16B)
    __shared__ __align__(16) float swigT[25*28];   // swigT[i][j] = wig[j][i]
    __shared__ __align__(16) float smrot[LL*128];  // msgrot, later rotated-back v
    __shared__ __align__(16) float sh[LL*64];
    __shared__ __align__(16) float sv[LL*128];
    __shared__ float srad[64], ssig[64], sattn[8];

    int s = senders[e], r = receivers[e];
    for (int i=t; i<700; i+=128){
        int row=i/28, col=i-row*28;
        swig[i]  = (col<25) ? wigner[(size_t)e*625 + row*25 + col] : 0.f;
        swigT[i] = (col<25) ? wigner[(size_t)e*625 + col*25 + row] : 0.f;
    }
    if (t < 64) srad[t] = g_rad[(size_t)e*64+t];
    if (t < 8){
        float lg = g_logits[(size_t)e*8+t];
        sattn[t] = __expf(lg - g_segmax[r*8+t]) / (g_denom[r*8+t] + EPSF);
    }
    __syncthreads();

    // gather my column of concat(x[s], x[r]) and rotate: smrot[i][t] = sum_j wig[i][j]*mc[j]
    float mc[28];
    {
        const float* xb = (t < 64) ? (g_x1 + (size_t)s*1600 + t)
                                   : (g_x1 + (size_t)r*1600 + (t-64));
        #pragma unroll
        for (int j=0; j<25; j++) mc[j] = xb[j*64];
        mc[25]=mc[26]=mc[27]=0.f;
    }
    #pragma unroll 1
    for (int i=0; i<25; i++){
        float acc = 0.f;
        #pragma unroll
        for (int q=0; q<7; q++){
            float4 w = *(const float4*)&swig[i*28 + 4*q];
            acc = fmaf(w.x, mc[4*q+0], acc);
            acc = fmaf(w.y, mc[4*q+1], acc);
            acc = fmaf(w.z, mc[4*q+2], acc);
            acc = fmaf(w.w, mc[4*q+3], acc);
        }
        smrot[i*128+t] = acc;
    }
    __syncthreads();

    // h0 (degree 0) + gate
    if (t < 64){
        float acc = 0.f;
        #pragma unroll 4
        for (int q=0; q<32; q++){
            float w0 = __ldg(&W_msg[(4*q+0)*64+t]);
            float w1 = __ldg(&W_msg[(4*q+1)*64+t]);
            float w2 = __ldg(&W_msg[(4*q+2)*64+t]);
            float w3 = __ldg(&W_msg[(4*q+3)*64+t]);
            float4 a = *(const float4*)&smrot[4*q];
            acc = fmaf(a.x,w0,fmaf(a.y,w1,fmaf(a.z,w2,fmaf(a.w,w3,acc))));
        }
        acc *= srad[t];
        float sg = sigmoidf_(acc);
        ssig[t] = sg;
        sh[t] = acc*sg;
    }
    __syncthreads();

    // remaining degrees, split across the two half-blocks (12 rows each)
    {
        int c = t & 63;
        float scale = srad[c]*ssig[c];
        if (t < 64){
            mm4_h<3>(smrot, W_msg + 1*8192, sh, 1,  c, scale);  // degree 1
            mm4_h<9>(smrot, W_msg + 4*8192, sh, 16, c, scale);  // degree 4
        } else {
            mm4_h<5>(smrot, W_msg + 2*8192, sh, 4,  c, scale);  // degree 2
            mm4_h<7>(smrot, W_msg + 3*8192, sh, 9,  c, scale);  // degree 3
        }
    }
    __syncthreads();

    // v = h @ W_val[deg], scaled by per-head attention (writes column t of sv)
    {
        float attn = sattn[t>>4];
        mm4_v<1>(sh, W_val + 0*8192, sv, 0,  t, attn);
        mm4_v<3>(sh, W_val + 1*8192, sv, 1,  t, attn);
        mm4_v<5>(sh, W_val + 2*8192, sv, 4,  t, attn);
        mm4_v<7>(sh, W_val + 3*8192, sv, 9,  t, attn);
        mm4_v<9>(sh, W_val + 4*8192, sv, 16, t, attn);
    }
    // rotate back with wigner^T: column t of sv -> column t of smrot (column-private, no sync)
    #pragma unroll
    for (int j=0; j<25; j++) mc[j] = sv[j*128+t];
    mc[25]=mc[26]=mc[27]=0.f;
    #pragma unroll 1
    for (int i=0; i<25; i++){
        float acc = 0.f;
        #pragma unroll
        for (int q=0; q<7; q++){
            float4 w = *(const float4*)&swigT[i*28 + 4*q];
            acc = fmaf(w.x, mc[4*q+0], acc);
            acc = fmaf(w.y, mc[4*q+1], acc);
            acc = fmaf(w.z, mc[4*q+2], acc);
            acc = fmaf(w.w, mc[4*q+3], acc);
        }
        smrot[i*128+t] = acc;
    }
    __syncthreads();

    // one bulk reduce-add of the whole 25x128 tile into g_agg[r]
    if (t == 0){
        asm volatile("fence.proxy.async.shared::cta;" ::: "memory");
        float* dst = g_agg + (size_t)r*3200;
        uint32_t sptr;
        asm("{ .reg .u64 tt; cvta.to.shared.u64 tt, %1; cvt.u32.u64 %0, tt; }"
            : "=r"(sptr) : "l"(smrot));
        asm volatile("cp.reduce.async.bulk.global.shared::cta.bulk_group.add.f32 [%0], [%1], %2;"
                     :: "l"(dst), "r"(sptr), "r"(12800) : "memory");
        asm volatile("cp.async.bulk.commit_group;" ::: "memory");
        asm volatile("cp.async.bulk.wait_group 0;" ::: "memory");
    }
    __syncthreads();
}

// x2 = agg @ W_out[deg] + node_feats
__global__ __launch_bounds__(128)
void k_wout(const float* __restrict__ nf, const float* __restrict__ W_out, int N){
    int n = blockIdx.x; int t = threadIdx.x;
    __shared__ __align__(16) float sagg[LL*128];
    {
        const float4* src = (const float4*)(g_agg + (size_t)n*3200);
        float4* dst4 = (float4*)sagg;
        for (int i=t; i<800; i+=128) dst4[i] = src[i];
    }
    __syncthreads();
    int c = t & 63;
    const float* res = nf + (size_t)n*1600;
    float* outp = g_x2 + (size_t)n*1600;
    if (t < 64){
        mm4_out<1>(sagg, W_out + 0*8192, res, outp, 0,  c);
        mm4_out<3>(sagg, W_out + 1*8192, res, outp, 1,  c);
        mm4_out<9>(sagg, W_out + 4*8192, res, outp, 16, c);
    } else {
        mm4_out<5>(sagg, W_out + 2*8192, res, outp, 4,  c);
        mm4_out<7>(sagg, W_out + 3*8192, res, outp, 9,  c);
    }
}

// FFN part A: norm2 -> ff1(regs) -> to_grid -> W_grid+silu -> g_gg
__global__ __launch_bounds__(128)
void k_ffn_a(const float* __restrict__ norm2w, const float* __restrict__ W_ff1,
             const float* __restrict__ to_grid, const float* __restrict__ W_grid,
             const float* __restrict__ b_grid, int N){
    int n = blockIdx.x; int t = threadIdx.x;
    __shared__ __align__(16) float sx[LL*64];
    __shared__ __align__(16) float sg[GG*128];
    __shared__ __align__(16) float stg[GG*28];   // to_grid padded rows
    __shared__ float ssq[5], sinv[5];

    if (t < 5) ssq[t] = 0.f;
    for (int i=t; i<GG*28; i+=128){
        int p=i/28, l=i-p*28;
        stg[i] = (l<25) ? __ldg(&to_grid[p*25+l]) : 0.f;
    }
    __syncthreads();

    const float* xb = g_x2 + (size_t)n*1600;
    #pragma unroll
    for (int d=0; d<5; d++){
        int b = d*d*64, cnt = (2*d+1)*64;
        float a = 0.f;
        for (int idx=t; idx<cnt; idx+=128){ float v = xb[b+idx]; sx[b+idx] = v; a += v*v; }
        #pragma unroll
        for (int off=16; off>0; off>>=1) a += __shfl_down_sync(0xffffffffu, a, off);
        if ((t & 31) == 0) atomicAdd(&ssq[d], a);
    }
    __syncthreads();
    if (t < 5) sinv[t] = rsqrtf(ssq[t] / ((2.f*t+1.f)*64.f) + EPSF);
    __syncthreads();
    for (int idx=t; idx<1600; idx+=128){
        int l = idx>>6, c = idx&63;
        int d = c_deg[l];
        sx[idx] *= sinv[d] * __ldg(&norm2w[d*64+c]);
    }
    __syncthreads();

    // ff1 into registers (thread t owns column t of [25][128])
    float t1[28];
    ff14_rows<1>(sx, W_ff1 + 0*8192, t1, 0,  t);
    ff14_rows<3>(sx, W_ff1 + 1*8192, t1, 1,  t);
    ff14_rows<5>(sx, W_ff1 + 2*8192, t1, 4,  t);
    ff14_rows<7>(sx, W_ff1 + 3*8192, t1, 9,  t);
    ff14_rows<9>(sx, W_ff1 + 4*8192, t1, 16, t);
    t1[25]=t1[26]=t1[27]=0.f;

    // to_grid: sg[p][t] = sum_l tg[p][l] * t1[l]
    #pragma unroll 1
    for (int p=0; p<GG; p++){
        float acc = 0.f;
        #pragma unroll
        for (int q=0; q<7; q++){
            float4 w = *(const float4*)&stg[p*28 + 4*q];
            acc = fmaf(w.x, t1[4*q+0], acc);
            acc = fmaf(w.y, t1[4*q+1], acc);
            acc = fmaf(w.z, t1[4*q+2], acc);
            acc = fmaf(w.w, t1[4*q+3], acc);
        }
        sg[p*128+t] = acc;
    }
    __syncthreads();

    // W_grid + silu, 5-row tiles (45 = 9*5)
    float bg = __ldg(&b_grid[t]);
    #pragma unroll 1
    for (int pt=0; pt<9; pt++){
        float acc[5] = {0.f,0.f,0.f,0.f,0.f};
        #pragma unroll 4
        for (int q=0; q<32; q++){
            float w0 = __ldg(&W_grid[(4*q+0)*128+t]);
            float w1 = __ldg(&W_grid[(4*q+1)*128+t]);
            float w2 = __ldg(&W_grid[(4*q+2)*128+t]);
            float w3 = __ldg(&W_grid[(4*q+3)*128+t]);
            #pragma unroll
            for (int rr=0; rr<5; rr++){
                float4 a = *(const float4*)&sg[(pt*5+rr)*128 + 4*q];
                acc[rr] = fmaf(a.x,w0,fmaf(a.y,w1,fmaf(a.z,w2,fmaf(a.w,w3,acc[rr]))));
            }
        }
        #pragma unroll
        for (int rr=0; rr<5; rr++){
            float z = acc[rr] + bg;
            g_gg[((size_t)n*GG + pt*5+rr)*128 + t] = z * sigmoidf_(z);
        }
    }
}

// FFN part B: from_grid(regs) -> ff2 + residual -> out
__global__ __launch_bounds__(128)
void k_ffn_b(const float* __restrict__ from_grid, const float* __restrict__ W_ff2,
             float* __restrict__ out, int N){
    int n = blockIdx.x; int t = threadIdx.x;
    __shared__ __align__(16) float sfg[LL*48];   // from_grid padded rows (192B = 12x16B)
    __shared__ __align__(16) float sy2[LL*128];

    for (int i=t; i<LL*48; i+=128){
        int l=i/48, p=i-l*48;
        sfg[i] = (p<GG) ? __ldg(&from_grid[l*GG+p]) : 0.f;
    }

    float gg[48];
    {
        const float* src = g_gg + (size_t)n*GG*128 + t;
        #pragma unroll
        for (int p=0; p<GG; p++) gg[p] = src[p*128];
        gg[45]=gg[46]=gg[47]=0.f;
    }
    __syncthreads();

    #pragma unroll 1
    for (int l=0; l<25; l++){
        float acc = 0.f;
        #pragma unroll
        for (int q=0; q<12; q++){
            float4 w = *(const float4*)&sfg[l*48 + 4*q];
            acc = fmaf(w.x, gg[4*q+0], acc);
            acc = fmaf(w.y, gg[4*q+1], acc);
            acc = fmaf(w.z, gg[4*q+2], acc);
            acc = fmaf(w.w, gg[4*q+3], acc);
        }
        sy2[l*128+t] = acc;
    }
    __syncthreads();

    int c = t & 63;
    const float* res = g_x2 + (size_t)n*1600;
    float* outp = out + (size_t)n*1600;
    if (t < 64){
        mm4_out<1>(sy2, W_ff2 + 0*8192, res, outp, 0,  c);
        mm4_out<3>(sy2, W_ff2 + 1*8192, res, outp, 1,  c);
        mm4_out<9>(sy2, W_ff2 + 4*8192, res, outp, 16, c);
    } else {
        mm4_out<5>(sy2, W_ff2 + 2*8192, res, outp, 4,  c);
        mm4_out<7>(sy2, W_ff2 + 3*8192, res, outp, 9,  c);
    }
}

// ---------------- host launcher ----------------
extern "C" void kernel_launch(void* const* d_in, const int* in_sizes, int n_in,
                              void* d_out, int out_size){
    int p = (in_sizes[6] <= 4) ? 7 : 6;

    const float* node_feats = (const float*)d_in[0];
    const int*   species    = (const int*)  d_in[1];
    const float* edge_dist  = (const float*)d_in[2];
    const int*   senders    = (const int*)  d_in[3];
    const int*   receivers  = (const int*)  d_in[4];
    const float* wigner     = (const float*)d_in[5];
    const float* norm1_w    = (const float*)d_in[p+0];
    const float* norm2_w    = (const float*)d_in[p+1];
    const float* W_edge     = (const float*)d_in[p+2];
    const float* emb_src    = (const float*)d_in[p+3];
    const float* emb_dst    = (const float*)d_in[p+4];
    const float* W_r1       = (const float*)d_in[p+5];
    const float* b_r1       = (const float*)d_in[p+6];
    const float* W_r2       = (const float*)d_in[p+7];
    const float* b_r2       = (const float*)d_in[p+8];
    const float* W_msg      = (const float*)d_in[p+9];
    const float* W_alpha    = (const float*)d_in[p+10];
    const float* alpha_vec  = (const float*)d_in[p+11];
    const float* W_val      = (const float*)d_in[p+12];
    const float* W_out      = (const float*)d_in[p+13];
    const float* W_ff1      = (const float*)d_in[p+14];
    const float* to_grid    = (const float*)d_in[p+15];
    const float* from_grid  = (const float*)d_in[p+16];
    const float* W_grid     = (const float*)d_in[p+17];
    const float* b_grid     = (const float*)d_in[p+18];
    const float* W_ff2      = (const float*)d_in[p+19];

    int N = in_sizes[0] / (LL*CC);
    int E = in_sizes[3];
    if (N > NMAX) N = NMAX;
    if (E > EMAX) E = EMAX;

    k_init<<<2048, 256>>>(N);
    k_norm1<<<N, 128>>>(node_feats, norm1_w, N);
    k_edge_logits<<<(E+1)/2, 128>>>(edge_dist, species, senders, receivers, wigner,
                                    W_edge, emb_src, emb_dst, W_r1, b_r1, W_r2, b_r2,
                                    W_msg, W_alpha, alpha_vec, E);
    int segthreads = 256;
    int segblocks = (E*8 + segthreads - 1) / segthreads;
    k_segmax<<<segblocks, segthreads>>>(receivers, E);
    k_denom<<<segblocks, segthreads>>>(receivers, E);
    k_edge_main<<<E, 128>>>(senders, receivers, wigner, W_msg, W_val, E);
    k_wout<<<N, 128>>>(node_feats, W_out, N);
    k_ffn_a<<<N, 128>>>(norm2_w, W_ff1, to_grid, W_grid, b_grid, N);
    k_ffn_b<<<N, 128>>>(from_grid, W_ff2, (float*)d_out, N);
}

// round 9
// speedup vs baseline: 2.4890x; 1.0460x over previous
#include <cuda_runtime.h>
#include <math.h>
#include <stdint.h>

#define LL 25
#define CC 64
#define NMAX 4096
#define EMAX 32768
#define GG 45
#define EPSF 1e-6f

typedef unsigned long long u64t;

__constant__ int c_deg[25] = {0,1,1,1,2,2,2,2,2,3,3,3,3,3,3,3,4,4,4,4,4,4,4,4,4};

// ---------------- scratch ----------------
__device__ float g_x1[(size_t)NMAX*LL*CC];
__device__ float g_rad[(size_t)EMAX*64];
__device__ float g_logits[(size_t)EMAX*8];
__device__ float g_segmax[NMAX*8];
__device__ float g_denom[NMAX*8];
__device__ float g_agg[(size_t)NMAX*LL*128];
__device__ float g_x2[(size_t)NMAX*LL*CC];
__device__ float g_gg[(size_t)NMAX*GG*128];

__device__ __forceinline__ float sigmoidf_(float x){ return 1.f/(1.f+__expf(-x)); }

__device__ __forceinline__ void atomicMaxF(float* addr, float v){
    if (v >= 0.f) atomicMax((int*)addr, __float_as_int(v));
    else          atomicMin((unsigned int*)addr, __float_as_uint(v));
}

// ---------------- packed f32x2 primitives ----------------
__device__ __forceinline__ u64t pk2(float lo, float hi){
    u64t r; asm("mov.b64 %0,{%1,%2};" : "=l"(r) : "f"(lo), "f"(hi)); return r;
}
__device__ __forceinline__ void fma2(u64t& d, u64t a, u64t b){
    asm("fma.rn.f32x2 %0,%1,%2,%0;" : "+l"(d) : "l"(a), "l"(b));
}
__device__ __forceinline__ float upsum(u64t v){
    float lo, hi; asm("mov.b64 {%0,%1},%2;" : "=f"(lo), "=f"(hi) : "l"(v)); return lo+hi;
}

// ---------------- f32x2 small-GEMM helpers ----------------
// A smem [rows][128] (16B-aligned rows), W [128][64], out smem [rows][64], scaled
template<int R>
__device__ __forceinline__ void mm2_h(const float* __restrict__ sA,
                                      const float* __restrict__ W,
                                      float* __restrict__ sOut,
                                      int base, int c, float scale){
    u64t acc[R];
    #pragma unroll
    for (int rr=0; rr<R; rr++) acc[rr] = 0ull;
    #pragma unroll 4
    for (int q=0; q<32; q++){
        u64t wA = pk2(__ldg(&W[(4*q+0)*64+c]), __ldg(&W[(4*q+1)*64+c]));
        u64t wB = pk2(__ldg(&W[(4*q+2)*64+c]), __ldg(&W[(4*q+3)*64+c]));
        #pragma unroll
        for (int rr=0; rr<R; rr++){
            ulonglong2 a = *(const ulonglong2*)&sA[(base+rr)*128 + 4*q];
            fma2(acc[rr], a.x, wA);
            fma2(acc[rr], a.y, wB);
        }
    }
    #pragma unroll
    for (int rr=0; rr<R; rr++) sOut[(base+rr)*64+c] = upsum(acc[rr])*scale;
}

// A smem [rows][64], W [64][128], out register array vr[base..base+R), scaled
template<int R>
__device__ __forceinline__ void mm2_v_reg(const float* __restrict__ sA,
                                          const float* __restrict__ W,
                                          float* __restrict__ vr,
                                          int base, int c, float scale){
    u64t acc[R];
    #pragma unroll
    for (int rr=0; rr<R; rr++) acc[rr] = 0ull;
    #pragma unroll 4
    for (int q=0; q<16; q++){
        u64t wA = pk2(__ldg(&W[(4*q+0)*128+c]), __ldg(&W[(4*q+1)*128+c]));
        u64t wB = pk2(__ldg(&W[(4*q+2)*128+c]), __ldg(&W[(4*q+3)*128+c]));
        #pragma unroll
        for (int rr=0; rr<R; rr++){
            ulonglong2 a = *(const ulonglong2*)&sA[(base+rr)*64 + 4*q];
            fma2(acc[rr], a.x, wA);
            fma2(acc[rr], a.y, wB);
        }
    }
    #pragma unroll
    for (int rr=0; rr<R; rr++) vr[base+rr] = upsum(acc[rr])*scale;
}

// A smem [rows][128], W [128][64], out global [rows][64] + residual
template<int R>
__device__ __forceinline__ void mm2_out(const float* __restrict__ sA,
                                        const float* __restrict__ W,
                                        const float* __restrict__ res,
                                        float* __restrict__ outp,
                                        int base, int c){
    u64t acc[R];
    #pragma unroll
    for (int rr=0; rr<R; rr++) acc[rr] = 0ull;
    #pragma unroll 4
    for (int q=0; q<32; q++){
        u64t wA = pk2(__ldg(&W[(4*q+0)*64+c]), __ldg(&W[(4*q+1)*64+c]));
        u64t wB = pk2(__ldg(&W[(4*q+2)*64+c]), __ldg(&W[(4*q+3)*64+c]));
        #pragma unroll
        for (int rr=0; rr<R; rr++){
            ulonglong2 a = *(const ulonglong2*)&sA[(base+rr)*128 + 4*q];
            fma2(acc[rr], a.x, wA);
            fma2(acc[rr], a.y, wB);
        }
    }
    #pragma unroll
    for (int rr=0; rr<R; rr++)
        outp[(base+rr)*64+c] = upsum(acc[rr]) + res[(base+rr)*64+c];
}

// A smem [rows][64], W [64][128], out regs t1[base..base+R)
template<int R>
__device__ __forceinline__ void ff2_rows(const float* __restrict__ sA,
                                         const float* __restrict__ W,
                                         float* __restrict__ t1,
                                         int base, int f){
    u64t acc[R];
    #pragma unroll
    for (int rr=0; rr<R; rr++) acc[rr] = 0ull;
    #pragma unroll 4
    for (int q=0; q<16; q++){
        u64t wA = pk2(__ldg(&W[(4*q+0)*128+f]), __ldg(&W[(4*q+1)*128+f]));
        u64t wB = pk2(__ldg(&W[(4*q+2)*128+f]), __ldg(&W[(4*q+3)*128+f]));
        #pragma unroll
        for (int rr=0; rr<R; rr++){
            ulonglong2 a = *(const ulonglong2*)&sA[(base+rr)*64 + 4*q];
            fma2(acc[rr], a.x, wA);
            fma2(acc[rr], a.y, wB);
        }
    }
    #pragma unroll
    for (int rr=0; rr<R; rr++) t1[base+rr] = upsum(acc[rr]);
}

// 64-wide dot: act smem row (16B aligned, 64 floats), W [64][64] col c, init bias
__device__ __forceinline__ float dot64_2(const float* __restrict__ sAct,
                                         const float* __restrict__ W,
                                         int c, float init){
    u64t acc = pk2(init, 0.f);
    #pragma unroll 4
    for (int q=0; q<16; q++){
        u64t wA = pk2(__ldg(&W[(4*q+0)*64+c]), __ldg(&W[(4*q+1)*64+c]));
        u64t wB = pk2(__ldg(&W[(4*q+2)*64+c]), __ldg(&W[(4*q+3)*64+c]));
        ulonglong2 a = *(const ulonglong2*)&sAct[4*q];
        fma2(acc, a.x, wA);
        fma2(acc, a.y, wB);
    }
    return upsum(acc);
}

// ---------------- kernels ----------------

__global__ void k_init(int N){
    int i = blockIdx.x*blockDim.x + threadIdx.x;
    int stride = gridDim.x*blockDim.x;
    int tot = N*LL*128;
    for (int idx=i; idx<tot; idx+=stride) g_agg[idx] = 0.f;
    if (i < N*8){ g_denom[i] = 0.f; g_segmax[i] = -1e30f; }
}

__global__ void k_norm1(const float* __restrict__ nf, const float* __restrict__ w, int N){
    int n = blockIdx.x; int t = threadIdx.x;
    __shared__ float ssq[5], sinv[5];
    if (t < 5) ssq[t] = 0.f;
    __syncthreads();
    const float* src = nf + (size_t)n*1600;
    #pragma unroll
    for (int d=0; d<5; d++){
        int b = d*d*64, cnt = (2*d+1)*64;
        float a = 0.f;
        for (int idx=t; idx<cnt; idx+=128){ float v = src[b+idx]; a += v*v; }
        #pragma unroll
        for (int off=16; off>0; off>>=1) a += __shfl_down_sync(0xffffffffu, a, off);
        if ((t & 31) == 0) atomicAdd(&ssq[d], a);
    }
    __syncthreads();
    if (t < 5) sinv[t] = rsqrtf(ssq[t] / ((2.f*t+1.f)*64.f) + EPSF);
    __syncthreads();
    float* dst = g_x1 + (size_t)n*1600;
    for (int idx=t; idx<1600; idx+=128){
        int l = idx>>6, c = idx&63;
        int d = c_deg[l];
        dst[idx] = src[idx] * sinv[d] * __ldg(&w[d*64+c]);
    }
}

// 2 edges per 128-thread block; each 64-thread sub-block runs all stages full-width.
__global__ __launch_bounds__(128)
void k_edge_logits(const float* __restrict__ dist, const int* __restrict__ species,
                   const int* __restrict__ senders, const int* __restrict__ receivers,
                   const float* __restrict__ wigner,
                   const float* __restrict__ W_edge, const float* __restrict__ emb_src,
                   const float* __restrict__ emb_dst,
                   const float* __restrict__ W_r1, const float* __restrict__ b_r1,
                   const float* __restrict__ W_r2, const float* __restrict__ b_r2,
                   const float* __restrict__ W_msg, const float* __restrict__ W_alpha,
                   const float* __restrict__ alpha_vec, int E){
    int t = threadIdx.x;
    int sub = t >> 6;
    int c = t & 63;
    int e = blockIdx.x*2 + sub;
    bool valid = (e < E);
    if (!valid) e = E-1;

    __shared__ __align__(16) float sdist[2][64], se[2][64], sr1[2][64], sm0[2][128], sh0[2][64];

    int s = senders[e], r = receivers[e];
    int sps = species[s], spr = species[r];
    sdist[sub][c] = dist[(size_t)e*64+c];
    __syncthreads();
    // stage 1: e = dist @ W_edge + embeddings
    se[sub][c] = dot64_2(&sdist[sub][0], W_edge, c,
                         __ldg(&emb_src[sps*64+c]) + __ldg(&emb_dst[spr*64+c]));
    __syncthreads();
    // stage 2: silu(e @ W_r1 + b1)
    {
        float acc = dot64_2(&se[sub][0], W_r1, c, __ldg(&b_r1[c]));
        sr1[sub][c] = acc * sigmoidf_(acc);
    }
    __syncthreads();
    // stage 3: rad = sr1 @ W_r2 + b2
    float rad = dot64_2(&sr1[sub][0], W_r2, c, __ldg(&b_r2[c]));
    g_rad[(size_t)e*64+c] = rad;
    // m0: row 0 of rotated concat message (each thread: both halves at column c)
    {
        const float* wg = wigner + (size_t)e*625;
        const float* xs = g_x1 + (size_t)s*1600 + c;
        const float* xr = g_x1 + (size_t)r*1600 + c;
        float a0=0.f, a1=0.f;
        #pragma unroll
        for (int j=0; j<25; j++){
            float w = __ldg(&wg[j]);
            a0 = fmaf(w, xs[j*64], a0);
            a1 = fmaf(w, xr[j*64], a1);
        }
        sm0[sub][c] = a0; sm0[sub][64+c] = a1;
    }
    __syncthreads();
    // h0 = (m0 @ W_msg[deg0]) * rad, gated
    {
        u64t acc2 = 0ull;
        #pragma unroll 4
        for (int q=0; q<32; q++){
            u64t wA = pk2(__ldg(&W_msg[(4*q+0)*64+c]), __ldg(&W_msg[(4*q+1)*64+c]));
            u64t wB = pk2(__ldg(&W_msg[(4*q+2)*64+c]), __ldg(&W_msg[(4*q+3)*64+c]));
            ulonglong2 a = *(const ulonglong2*)&sm0[sub][4*q];
            fma2(acc2, a.x, wA);
            fma2(acc2, a.y, wB);
        }
        float acc = upsum(acc2) * rad;
        sh0[sub][c] = acc * sigmoidf_(acc);
    }
    __syncthreads();
    // alpha: two outputs per thread (o=c, o=c+64), then 16-lane head reduction
    {
        u64t ac0 = 0ull, ac1 = 0ull;
        #pragma unroll 4
        for (int q=0; q<16; q++){
            ulonglong2 hv = *(const ulonglong2*)&sh0[sub][4*q];
            u64t wA0 = pk2(__ldg(&W_alpha[(4*q+0)*128+c]),    __ldg(&W_alpha[(4*q+1)*128+c]));
            u64t wB0 = pk2(__ldg(&W_alpha[(4*q+2)*128+c]),    __ldg(&W_alpha[(4*q+3)*128+c]));
            u64t wA1 = pk2(__ldg(&W_alpha[(4*q+0)*128+c+64]), __ldg(&W_alpha[(4*q+1)*128+c+64]));
            u64t wB1 = pk2(__ldg(&W_alpha[(4*q+2)*128+c+64]), __ldg(&W_alpha[(4*q+3)*128+c+64]));
            fma2(ac0, hv.x, wA0); fma2(ac0, hv.y, wB0);
            fma2(ac1, hv.x, wA1); fma2(ac1, hv.y, wB1);
        }
        float a0 = upsum(ac0), a1 = upsum(ac1);
        a0 = (a0 > 0.f) ? a0 : 0.2f*a0;
        a1 = (a1 > 0.f) ? a1 : 0.2f*a1;
        float p0 = a0 * __ldg(&alpha_vec[c]);
        float p1 = a1 * __ldg(&alpha_vec[c+64]);
        #pragma unroll
        for (int off=8; off>0; off>>=1){
            p0 += __shfl_down_sync(0xffffffffu, p0, off);
            p1 += __shfl_down_sync(0xffffffffu, p1, off);
        }
        if (((t & 15) == 0) && valid){
            g_logits[(size_t)e*8 + (c>>4)]     = p0;
            g_logits[(size_t)e*8 + 4 + (c>>4)] = p1;
        }
    }
}

__global__ void k_segmax(const int* __restrict__ receivers, int E){
    int i = blockIdx.x*blockDim.x + threadIdx.x;
    if (i >= E*8) return;
    int e = i>>3, hh = i&7;
    atomicMaxF(&g_segmax[receivers[e]*8+hh], g_logits[i]);
}

__global__ void k_denom(const int* __restrict__ receivers, int E){
    int i = blockIdx.x*blockDim.x + threadIdx.x;
    if (i >= E*8) return;
    int e = i>>3, hh = i&7;
    int r = receivers[e];
    atomicAdd(&g_denom[r*8+hh], __expf(g_logits[i] - g_segmax[r*8+hh]));
}

// main edge kernel
__global__ __launch_bounds__(128)
void k_edge_main(const int* __restrict__ senders, const int* __restrict__ receivers,
                 const float* __restrict__ wigner,
                 const float* __restrict__ W_msg, const float* __restrict__ W_val, int E){
    int e = blockIdx.x; int t = threadIdx.x;
    int c = t & 63;
    __shared__ __align__(16) float swig[25*28];    // padded rows (112B = 7x16B)
    __shared__ __align__(16) float swigT[25*28];   // swigT[i][j] = wig[j][i]
    __shared__ __align__(16) float smrot[LL*128];  // msgrot, later rotated-back v
    __shared__ __align__(16) float sh[LL*64];
    __shared__ float sattn[8];

    int s = senders[e], r = receivers[e];
    for (int i=t; i<700; i+=128){
        int row=i/28, col=i-row*28;
        swig[i]  = (col<25) ? wigner[(size_t)e*625 + row*25 + col] : 0.f;
        swigT[i] = (col<25) ? wigner[(size_t)e*625 + col*25 + row] : 0.f;
    }
    if (t < 8){
        float lg = g_logits[(size_t)e*8+t];
        sattn[t] = __expf(lg - g_segmax[r*8+t]) / (g_denom[r*8+t] + EPSF);
    }
    float rad = g_rad[(size_t)e*64+c];
    __syncthreads();

    // gather my column of concat(x[s], x[r]), pack, rotate: smrot[i][t] = sum_j wig[i][j]*mc[j]
    u64t mcp[14];
    {
        const float* xb = (t < 64) ? (g_x1 + (size_t)s*1600 + t)
                                   : (g_x1 + (size_t)r*1600 + (t-64));
        float mc[28];
        #pragma unroll
        for (int j=0; j<25; j++) mc[j] = xb[j*64];
        mc[25]=mc[26]=mc[27]=0.f;
        #pragma unroll
        for (int qq=0; qq<14; qq++) mcp[qq] = pk2(mc[2*qq], mc[2*qq+1]);
    }
    #pragma unroll 1
    for (int i=0; i<25; i++){
        u64t acc2 = 0ull;
        #pragma unroll
        for (int q=0; q<7; q++){
            ulonglong2 w = *(const ulonglong2*)&swig[i*28 + 4*q];
            fma2(acc2, w.x, mcp[2*q]);
            fma2(acc2, w.y, mcp[2*q+1]);
        }
        smrot[i*128+t] = upsum(acc2);
    }
    __syncthreads();

    // h0 (degree 0) + gate — computed redundantly by both halves for own column c
    float scale;
    {
        u64t acc2 = 0ull;
        #pragma unroll 4
        for (int q=0; q<32; q++){
            u64t wA = pk2(__ldg(&W_msg[(4*q+0)*64+c]), __ldg(&W_msg[(4*q+1)*64+c]));
            u64t wB = pk2(__ldg(&W_msg[(4*q+2)*64+c]), __ldg(&W_msg[(4*q+3)*64+c]));
            ulonglong2 a = *(const ulonglong2*)&smrot[4*q];
            fma2(acc2, a.x, wA);
            fma2(acc2, a.y, wB);
        }
        float h0 = upsum(acc2) * rad;
        float sg = sigmoidf_(h0);
        scale = rad * sg;
        if (t < 64) sh[c] = h0 * sg;
    }
    // remaining degrees, split across the two half-blocks (12 rows each)
    if (t < 64){
        mm2_h<3>(smrot, W_msg + 1*8192, sh, 1,  c, scale);  // degree 1
        mm2_h<9>(smrot, W_msg + 4*8192, sh, 16, c, scale);  // degree 4
    } else {
        mm2_h<5>(smrot, W_msg + 2*8192, sh, 4,  c, scale);  // degree 2
        mm2_h<7>(smrot, W_msg + 3*8192, sh, 9,  c, scale);  // degree 3
    }
    __syncthreads();

    // v = h @ W_val[deg] * attn, into registers (column t is thread-private)
    float vr[28];
    {
        float attn = sattn[t>>4];
        mm2_v_reg<1>(sh, W_val + 0*8192, vr, 0,  t, attn);
        mm2_v_reg<3>(sh, W_val + 1*8192, vr, 1,  t, attn);
        mm2_v_reg<5>(sh, W_val + 2*8192, vr, 4,  t, attn);
        mm2_v_reg<7>(sh, W_val + 3*8192, vr, 9,  t, attn);
        mm2_v_reg<9>(sh, W_val + 4*8192, vr, 16, t, attn);
    }
    vr[25]=vr[26]=vr[27]=0.f;
    // rotate back with wigner^T (column-private write into smrot; no sync needed)
    {
        u64t vrp[14];
        #pragma unroll
        for (int qq=0; qq<14; qq++) vrp[qq] = pk2(vr[2*qq], vr[2*qq+1]);
        #pragma unroll 1
        for (int i=0; i<25; i++){
            u64t acc2 = 0ull;
            #pragma unroll
            for (int q=0; q<7; q++){
                ulonglong2 w = *(const ulonglong2*)&swigT[i*28 + 4*q];
                fma2(acc2, w.x, vrp[2*q]);
                fma2(acc2, w.y, vrp[2*q+1]);
            }
            smrot[i*128+t] = upsum(acc2);
        }
    }
    __syncthreads();

    // one bulk reduce-add of the whole 25x128 tile into g_agg[r]
    if (t == 0){
        asm volatile("fence.proxy.async.shared::cta;" ::: "memory");
        float* dst = g_agg + (size_t)r*3200;
        uint32_t sptr;
        asm("{ .reg .u64 tt; cvta.to.shared.u64 tt, %1; cvt.u32.u64 %0, tt; }"
            : "=r"(sptr) : "l"(smrot));
        asm volatile("cp.reduce.async.bulk.global.shared::cta.bulk_group.add.f32 [%0], [%1], %2;"
                     :: "l"(dst), "r"(sptr), "r"(12800) : "memory");
        asm volatile("cp.async.bulk.commit_group;" ::: "memory");
        asm volatile("cp.async.bulk.wait_group 0;" ::: "memory");
    }
    __syncthreads();
}

// x2 = agg @ W_out[deg] + node_feats
__global__ __launch_bounds__(128)
void k_wout(const float* __restrict__ nf, const float* __restrict__ W_out, int N){
    int n = blockIdx.x; int t = threadIdx.x;
    __shared__ __align__(16) float sagg[LL*128];
    {
        const float4* src = (const float4*)(g_agg + (size_t)n*3200);
        float4* dst4 = (float4*)sagg;
        for (int i=t; i<800; i+=128) dst4[i] = src[i];
    }
    __syncthreads();
    int c = t & 63;
    const float* res = nf + (size_t)n*1600;
    float* outp = g_x2 + (size_t)n*1600;
    if (t < 64){
        mm2_out<1>(sagg, W_out + 0*8192, res, outp, 0,  c);
        mm2_out<3>(sagg, W_out + 1*8192, res, outp, 1,  c);
        mm2_out<9>(sagg, W_out + 4*8192, res, outp, 16, c);
    } else {
        mm2_out<5>(sagg, W_out + 2*8192, res, outp, 4,  c);
        mm2_out<7>(sagg, W_out + 3*8192, res, outp, 9,  c);
    }
}

// FFN part A: norm2 -> ff1(regs) -> to_grid -> W_grid+silu -> g_gg
__global__ __launch_bounds__(128)
void k_ffn_a(const float* __restrict__ norm2w, const float* __restrict__ W_ff1,
             const float* __restrict__ to_grid, const float* __restrict__ W_grid,
             const float* __restrict__ b_grid, int N){
    int n = blockIdx.x; int t = threadIdx.x;
    __shared__ __align__(16) float sx[LL*64];
    __shared__ __align__(16) float sg[GG*128];
    __shared__ __align__(16) float stg[GG*28];   // to_grid padded rows
    __shared__ float ssq[5], sinv[5];

    if (t < 5) ssq[t] = 0.f;
    for (int i=t; i<GG*28; i+=128){
        int p=i/28, l=i-p*28;
        stg[i] = (l<25) ? __ldg(&to_grid[p*25+l]) : 0.f;
    }
    __syncthreads();

    const float* xb = g_x2 + (size_t)n*1600;
    #pragma unroll
    for (int d=0; d<5; d++){
        int b = d*d*64, cnt = (2*d+1)*64;
        float a = 0.f;
        for (int idx=t; idx<cnt; idx+=128){ float v = xb[b+idx]; sx[b+idx] = v; a += v*v; }
        #pragma unroll
        for (int off=16; off>0; off>>=1) a += __shfl_down_sync(0xffffffffu, a, off);
        if ((t & 31) == 0) atomicAdd(&ssq[d], a);
    }
    __syncthreads();
    if (t < 5) sinv[t] = rsqrtf(ssq[t] / ((2.f*t+1.f)*64.f) + EPSF);
    __syncthreads();
    for (int idx=t; idx<1600; idx+=128){
        int l = idx>>6, c = idx&63;
        int d = c_deg[l];
        sx[idx] *= sinv[d] * __ldg(&norm2w[d*64+c]);
    }
    __syncthreads();

    // ff1 into registers (thread t owns column t of [25][128])
    float t1[28];
    ff2_rows<1>(sx, W_ff1 + 0*8192, t1, 0,  t);
    ff2_rows<3>(sx, W_ff1 + 1*8192, t1, 1,  t);
    ff2_rows<5>(sx, W_ff1 + 2*8192, t1, 4,  t);
    ff2_rows<7>(sx, W_ff1 + 3*8192, t1, 9,  t);
    ff2_rows<9>(sx, W_ff1 + 4*8192, t1, 16, t);
    t1[25]=t1[26]=t1[27]=0.f;

    // to_grid: sg[p][t] = sum_l tg[p][l] * t1[l]
    {
        u64t t1p[14];
        #pragma unroll
        for (int qq=0; qq<14; qq++) t1p[qq] = pk2(t1[2*qq], t1[2*qq+1]);
        #pragma unroll 1
        for (int p=0; p<GG; p++){
            u64t acc2 = 0ull;
            #pragma unroll
            for (int q=0; q<7; q++){
                ulonglong2 w = *(const ulonglong2*)&stg[p*28 + 4*q];
                fma2(acc2, w.x, t1p[2*q]);
                fma2(acc2, w.y, t1p[2*q+1]);
            }
            sg[p*128+t] = upsum(acc2);
        }
    }
    __syncthreads();

    // W_grid + silu, 5-row tiles (45 = 9*5)
    float bg = __ldg(&b_grid[t]);
    #pragma unroll 1
    for (int pt=0; pt<9; pt++){
        u64t acc[5];
        #pragma unroll
        for (int rr=0; rr<5; rr++) acc[rr] = 0ull;
        #pragma unroll 4
        for (int q=0; q<32; q++){
            u64t wA = pk2(__ldg(&W_grid[(4*q+0)*128+t]), __ldg(&W_grid[(4*q+1)*128+t]));
            u64t wB = pk2(__ldg(&W_grid[(4*q+2)*128+t]), __ldg(&W_grid[(4*q+3)*128+t]));
            #pragma unroll
            for (int rr=0; rr<5; rr++){
                ulonglong2 a = *(const ulonglong2*)&sg[(pt*5+rr)*128 + 4*q];
                fma2(acc[rr], a.x, wA);
                fma2(acc[rr], a.y, wB);
            }
        }
        #pragma unroll
        for (int rr=0; rr<5; rr++){
            float z = upsum(acc[rr]) + bg;
            g_gg[((size_t)n*GG + pt*5+rr)*128 + t] = z * sigmoidf_(z);
        }
    }
}

// FFN part B: from_grid(regs) -> ff2 + residual -> out
__global__ __launch_bounds__(128)
void k_ffn_b(const float* __restrict__ from_grid, const float* __restrict__ W_ff2,
             float* __restrict__ out, int N){
    int n = blockIdx.x; int t = threadIdx.x;
    __shared__ __align__(16) float sfg[LL*48];   // from_grid padded rows (192B = 12x16B)
    __shared__ __align__(16) float sy2[LL*128];

    for (int i=t; i<LL*48; i+=128){
        int l=i/48, p=i-l*48;
        sfg[i] = (p<GG) ? __ldg(&from_grid[l*GG+p]) : 0.f;
    }

    u64t ggp[24];
    {
        const float* src = g_gg + (size_t)n*GG*128 + t;
        float gg[48];
        #pragma unroll
        for (int p=0; p<GG; p++) gg[p] = src[p*128];
        gg[45]=gg[46]=gg[47]=0.f;
        #pragma unroll
        for (int qq=0; qq<24; qq++) ggp[qq] = pk2(gg[2*qq], gg[2*qq+1]);
    }
    __syncthreads();

    #pragma unroll 1
    for (int l=0; l<25; l++){
        u64t acc2 = 0ull;
        #pragma unroll
        for (int q=0; q<12; q++){
            ulonglong2 w = *(const ulonglong2*)&sfg[l*48 + 4*q];
            fma2(acc2, w.x, ggp[2*q]);
            fma2(acc2, w.y, ggp[2*q+1]);
        }
        sy2[l*128+t] = upsum(acc2);
    }
    __syncthreads();

    int c = t & 63;
    const float* res = g_x2 + (size_t)n*1600;
    float* outp = out + (size_t)n*1600;
    if (t < 64){
        mm2_out<1>(sy2, W_ff2 + 0*8192, res, outp, 0,  c);
        mm2_out<3>(sy2, W_ff2 + 1*8192, res, outp, 1,  c);
        mm2_out<9>(sy2, W_ff2 + 4*8192, res, outp, 16, c);
    } else {
        mm2_out<5>(sy2, W_ff2 + 2*8192, res, outp, 4,  c);
        mm2_out<7>(sy2, W_ff2 + 3*8192, res, outp, 9,  c);
    }
}

// ---------------- host launcher ----------------
extern "C" void kernel_launch(void* const* d_in, const int* in_sizes, int n_in,
                              void* d_out, int out_size){
    int p = (in_sizes[6] <= 4) ? 7 : 6;

    const float* node_feats = (const float*)d_in[0];
    const int*   species    = (const int*)  d_in[1];
    const float* edge_dist  = (const float*)d_in[2];
    const int*   senders    = (const int*)  d_in[3];
    const int*   receivers  = (const int*)  d_in[4];
    const float* wigner     = (const float*)d_in[5];
    const float* norm1_w    = (const float*)d_in[p+0];
    const float* norm2_w    = (const float*)d_in[p+1];
    const float* W_edge     = (const float*)d_in[p+2];
    const float* emb_src    = (const float*)d_in[p+3];
    const float* emb_dst    = (const float*)d_in[p+4];
    const float* W_r1       = (const float*)d_in[p+5];
    const float* b_r1       = (const float*)d_in[p+6];
    const float* W_r2       = (const float*)d_in[p+7];
    const float* b_r2       = (const float*)d_in[p+8];
    const float* W_msg      = (const float*)d_in[p+9];
    const float* W_alpha    = (const float*)d_in[p+10];
    const float* alpha_vec  = (const float*)d_in[p+11];
    const float* W_val      = (const float*)d_in[p+12];
    const float* W_out      = (const float*)d_in[p+13];
    const float* W_ff1      = (const float*)d_in[p+14];
    const float* to_grid    = (const float*)d_in[p+15];
    const float* from_grid  = (const float*)d_in[p+16];
    const float* W_grid     = (const float*)d_in[p+17];
    const float* b_grid     = (const float*)d_in[p+18];
    const float* W_ff2      = (const float*)d_in[p+19];

    int N = in_sizes[0] / (LL*CC);
    int E = in_sizes[3];
    if (N > NMAX) N = NMAX;
    if (E > EMAX) E = EMAX;

    k_init<<<2048, 256>>>(N);
    k_norm1<<<N, 128>>>(node_feats, norm1_w, N);
    k_edge_logits<<<(E+1)/2, 128>>>(edge_dist, species, senders, receivers, wigner,
                                    W_edge, emb_src, emb_dst, W_r1, b_r1, W_r2, b_r2,
                                    W_msg, W_alpha, alpha_vec, E);
    int segthreads = 256;
    int segblocks = (E*8 + segthreads - 1) / segthreads;
    k_segmax<<<segblocks, segthreads>>>(receivers, E);
    k_denom<<<segblocks, segthreads>>>(receivers, E);
    k_edge_main<<<E, 128>>>(senders, receivers, wigner, W_msg, W_val, E);
    k_wout<<<N, 128>>>(node_feats, W_out, N);
    k_ffn_a<<<N, 128>>>(norm2_w, W_ff1, to_grid, W_grid, b_grid, N);
    k_ffn_b<<<N, 128>>>(from_grid, W_ff2, (float*)d_out, N);
}